// round 15
// baseline (speedup 1.0000x reference)
#include <cuda_runtime.h>
#include <cuda_fp16.h>
#include <stdint.h>
#include <math.h>

#define B_   2
#define S_   1024
#define D_   1024
#define H_   16
#define DH_  64
#define FF_  4096
#define V_   32000
#define L_   4
#define PAD_ 3
#define CTX_ 1025

// ---------------- scratch (fp32) ----------------------------------------------
__device__ float g_x  [B_*S_*D_];
__device__ float g_xn [B_*S_*D_];

// ---------------- fp16 weights + activations -----------------------------------
__device__ __align__(16) __half h_Wq [L_*D_*D_];
__device__ __align__(16) __half h_Wk [L_*D_*D_];
__device__ __align__(16) __half h_Wv [L_*D_*D_];
__device__ __align__(16) __half h_Wr [L_*D_*D_];
__device__ __align__(16) __half h_Wfc[L_*D_*D_];
__device__ __align__(16) __half h_W1 [L_*D_*FF_];
__device__ __align__(16) __half h_W2 [L_*FF_*D_];
__device__ __align__(16) __half h_Wlm[(size_t)D_*V_];
__device__ __align__(16) __half h_xn [B_*S_*D_];
__device__ __align__(16) __half h_rel[S_*D_];
__device__ __align__(16) __half h_o  [B_*S_*D_];
__device__ __align__(16) __half h_ff [B_*S_*FF_];
__device__ __align__(16) __half h_q  [B_*S_*D_];
__device__ __align__(16) __half h_k  [B_*S_*D_];
__device__ __align__(16) __half h_v  [B_*S_*D_];
__device__ __align__(16) __half h_r  [S_*D_];

// ---------------- helpers --------------------------------------------------
__device__ __forceinline__ float gelu_t(float x){
    return 0.5f*x*(1.0f + tanhf(0.7978845608028654f*(x + 0.044715f*x*x*x)));
}
__device__ __forceinline__ uint32_t smaddr(const void* p){
    return (uint32_t)__cvta_generic_to_shared(p);
}
__device__ __forceinline__ void cp16(void* smem, const void* gmem){
    asm volatile("cp.async.cg.shared.global [%0], [%1], 16;\n"
        :: "r"(smaddr(smem)), "l"(gmem));
}
#define CP_COMMIT() asm volatile("cp.async.commit_group;\n" ::: "memory")
#define CP_WAIT(N)  asm volatile("cp.async.wait_group %0;\n" :: "n"(N) : "memory")

__device__ __forceinline__ void mma_f16(float c[4], const uint32_t a[4], const uint32_t b0, const uint32_t b1){
    asm volatile(
      "mma.sync.aligned.m16n8k16.row.col.f32.f16.f16.f32 "
      "{%0,%1,%2,%3}, {%4,%5,%6,%7}, {%8,%9}, {%0,%1,%2,%3};\n"
      : "+f"(c[0]), "+f"(c[1]), "+f"(c[2]), "+f"(c[3])
      : "r"(a[0]), "r"(a[1]), "r"(a[2]), "r"(a[3]), "r"(b0), "r"(b1));
}
__device__ __forceinline__ void ldsm_x4(uint32_t r[4], uint32_t addr){
    asm volatile("ldmatrix.sync.aligned.m8n8.x4.shared.b16 {%0,%1,%2,%3}, [%4];"
      : "=r"(r[0]), "=r"(r[1]), "=r"(r[2]), "=r"(r[3]) : "r"(addr));
}
__device__ __forceinline__ void ldsm_x4_t(uint32_t r[4], uint32_t addr){
    asm volatile("ldmatrix.sync.aligned.m8n8.x4.trans.shared.b16 {%0,%1,%2,%3}, [%4];"
      : "=r"(r[0]), "=r"(r[1]), "=r"(r[2]), "=r"(r[3]) : "r"(addr));
}

// ---------------- merged fp32 -> fp16 weight convert -------------------------
#define N8_DD (L_*D_*D_/8)
#define N8_DF (L_*D_*FF_/8)
#define N8_LM (D_*V_/8)
#define N8_TOTAL (5*N8_DD + 2*N8_DF + N8_LM)

__global__ void cvt_all_kernel(
    const float4* __restrict__ Wq,  const float4* __restrict__ Wk,
    const float4* __restrict__ Wv,  const float4* __restrict__ Wr,
    const float4* __restrict__ Wfc, const float4* __restrict__ W1,
    const float4* __restrict__ W2,  const float4* __restrict__ Wlm)
{
    int i = blockIdx.x*256 + threadIdx.x;
    const float4* src; uint4* dst; size_t j;
    if (i < 5*N8_DD){
        int t = i / N8_DD; j = i - t*N8_DD;
        src = (t==0)?Wq:(t==1)?Wk:(t==2)?Wv:(t==3)?Wr:Wfc;
        dst = (t==0)?(uint4*)h_Wq:(t==1)?(uint4*)h_Wk:(t==2)?(uint4*)h_Wv:(t==3)?(uint4*)h_Wr:(uint4*)h_Wfc;
    } else if (i < 5*N8_DD + 2*N8_DF){
        int k = i - 5*N8_DD; int t = k / N8_DF; j = k - t*N8_DF;
        src = t ? W2 : W1;
        dst = t ? (uint4*)h_W2 : (uint4*)h_W1;
    } else {
        j = i - (5*N8_DD + 2*N8_DF);
        src = Wlm; dst = (uint4*)h_Wlm;
    }
    float4 a = src[j*2], b = src[j*2+1];
    __half2 h0 = __floats2half2_rn(a.x, a.y);
    __half2 h1 = __floats2half2_rn(a.z, a.w);
    __half2 h2 = __floats2half2_rn(b.x, b.y);
    __half2 h3 = __floats2half2_rn(b.z, b.w);
    dst[j] = make_uint4(*(uint32_t*)&h0, *(uint32_t*)&h1, *(uint32_t*)&h2, *(uint32_t*)&h3);
}

// ---------------- embedding ------------------------------------------------
__global__ void embed_kernel(const int* __restrict__ text, const float* __restrict__ emb){
    int idx = blockIdx.x*256 + threadIdx.x;
    int d4  = idx & (D_/4 - 1);
    int bs  = idx >> 8;
    int s   = bs & (S_-1);
    int b   = bs >> 10;
    int tok = text[b*CTX_ + s];
    ((float4*)g_x)[idx] = ((const float4*)(emb + (size_t)tok*D_))[d4];
}

// ---------------- sinusoidal relative positions (fp16 out) ------------------
__global__ void rel_kernel(){
    int idx = blockIdx.x*256 + threadIdx.x;
    int j = idx & 511;
    int s = idx >> 9;
    float pos  = (float)(S_-1-s);
    float invf = powf(10000.0f, -(float)(2*j)/(float)D_);
    float a = pos*invf;
    h_rel[s*D_ + j]       = __float2half_rn(sinf(a));
    h_rel[s*D_ + j + 512] = __float2half_rn(cosf(a));
}

// ---------------- layernorm (fp16 out; optional fp32 out) --------------------
__global__ void ln_kernel(const float* __restrict__ in, float* __restrict__ out,
                          __half* __restrict__ out16,
                          const float* __restrict__ gam, const float* __restrict__ bet,
                          int write32){
    int row = blockIdx.x;
    int t = threadIdx.x;
    const float4* x4 = (const float4*)(in + (size_t)row*D_);
    float4 v = x4[t];
    float s  = v.x+v.y+v.z+v.w;
    float s2 = v.x*v.x+v.y*v.y+v.z*v.z+v.w*v.w;
    #pragma unroll
    for (int o=16;o;o>>=1){ s += __shfl_xor_sync(0xffffffffu,s,o); s2 += __shfl_xor_sync(0xffffffffu,s2,o); }
    __shared__ float shs[8], shs2[8], bc[2];
    int w = t>>5, lane = t&31;
    if (!lane){ shs[w]=s; shs2[w]=s2; }
    __syncthreads();
    if (t==0){
        float ts=0.f, ts2=0.f;
        #pragma unroll
        for (int i=0;i<8;i++){ ts+=shs[i]; ts2+=shs2[i]; }
        float m   = ts*(1.0f/(float)D_);
        float var = ts2*(1.0f/(float)D_) - m*m;
        bc[0]=m; bc[1]=rsqrtf(var + 1e-5f);
    }
    __syncthreads();
    float m = bc[0], inv = bc[1];
    float4 gg = ((const float4*)gam)[t];
    float4 bb = ((const float4*)bet)[t];
    float4 o4;
    o4.x = (v.x-m)*inv*gg.x + bb.x;
    o4.y = (v.y-m)*inv*gg.y + bb.y;
    o4.z = (v.z-m)*inv*gg.z + bb.z;
    o4.w = (v.w-m)*inv*gg.w + bb.w;
    if (write32)
        ((float4*)(out + (size_t)row*D_))[t] = o4;
    __half2 p0 = __floats2half2_rn(o4.x, o4.y);
    __half2 p1 = __floats2half2_rn(o4.z, o4.w);
    *(uint2*)(out16 + (size_t)row*D_ + t*4) = make_uint2(*(uint32_t*)&p0, *(uint32_t*)&p1);
}

// ================= fp16 GEMM with cp.async 4-stage pipeline (TBN=128) ========
#define TBM 128
#define TBN 128
#define TBK 32
#define STAGES 4
#define HG_SMEM ((STAGES*TBM*40 + STAGES*TBK*136)*2)

// EPI: 0 plain | 1 +bias | 2 gelu(acc+bias) | 3 R1+R2+acc+bias | 4 R1+gelu(acc+bias)
template<int EPI, typename TC>
__device__ __forceinline__ void hgemm_body(
    const __half* __restrict__ A, const __half* __restrict__ Bm,
    const float* __restrict__ bias, TC* __restrict__ C,
    const float* __restrict__ R1, const float* __restrict__ R2,
    int N, int K)
{
    extern __shared__ __half hsm[];
    __half* Asm = hsm;
    __half* Bsm = hsm + STAGES*TBM*40;

    const int tid = threadIdx.x;
    const int lane = tid & 31, wid = tid >> 5;
    const int wm = wid >> 1, wn = wid & 1;
    const int r = lane >> 2, cg = lane & 3;
    const int bm = blockIdx.x*TBM, bn = blockIdx.y*TBN;

    const int arow = tid >> 1, ac0 = (tid & 1)*16;
    const int brow = tid >> 3, bc0 = (tid & 7)*16;

    const int aRowL = lane & 15, aKH = lane >> 4;
    const int bKL   = (lane & 7) + ((lane >> 3) & 1)*8, bNH = lane >> 4;

    float acc[2][8][4];
    #pragma unroll
    for (int mt=0;mt<2;mt++)
        #pragma unroll
        for (int nt=0;nt<8;nt++)
            #pragma unroll
            for (int i=0;i<4;i++) acc[mt][nt][i]=0.f;

    const int nkt = K/TBK;

    auto issue = [&](int kt, int s){
        __half* as = Asm + (s*TBM + arow)*40 + ac0;
        const __half* ap = A + (size_t)(bm+arow)*K + kt*TBK + ac0;
        cp16(as,   ap);
        cp16(as+8, ap+8);
        __half* bs = Bsm + (s*TBK + brow)*136 + bc0;
        const __half* bp = Bm + (size_t)(kt*TBK + brow)*N + bn + bc0;
        cp16(bs,   bp);
        cp16(bs+8, bp+8);
    };

    #pragma unroll
    for (int s=0; s<STAGES-1; s++){ issue(s, s); CP_COMMIT(); }

    for (int kt=0; kt<nkt; kt++){
        CP_WAIT(STAGES-2);
        __syncthreads();
        const int nk = kt + STAGES-1;
        if (nk < nkt) issue(nk, nk & (STAGES-1));
        CP_COMMIT();

        const int s = kt & (STAGES-1);
        const __half* as = Asm + (size_t)s*TBM*40;
        const __half* bs = Bsm + (size_t)s*TBK*136;
        #pragma unroll
        for (int ks=0; ks<2; ks++){
            uint32_t af[2][4];
            #pragma unroll
            for (int mt=0;mt<2;mt++)
                ldsm_x4(af[mt], smaddr(as + (wm*32 + mt*16 + aRowL)*40 + ks*16 + aKH*8));
            #pragma unroll
            for (int nt=0;nt<4;nt++){
                uint32_t bf[4];
                ldsm_x4_t(bf, smaddr(bs + (ks*16 + bKL)*136 + wn*64 + nt*16 + bNH*8));
                mma_f16(acc[0][nt*2+0], af[0], bf[0], bf[1]);
                mma_f16(acc[1][nt*2+0], af[1], bf[0], bf[1]);
                mma_f16(acc[0][nt*2+1], af[0], bf[2], bf[3]);
                mma_f16(acc[1][nt*2+1], af[1], bf[2], bf[3]);
            }
        }
    }

    #pragma unroll
    for (int mt=0;mt<2;mt++){
        int row0 = bm + wm*32 + mt*16 + r;
        #pragma unroll
        for (int nt=0;nt<8;nt++){
            int col = bn + wn*64 + nt*8 + cg*2;
            float2 b2 = make_float2(0.f,0.f);
            if (EPI >= 1) b2 = *(const float2*)(bias + col);
            float2 v0, v1;
            v0.x = acc[mt][nt][0] + b2.x; v0.y = acc[mt][nt][1] + b2.y;
            v1.x = acc[mt][nt][2] + b2.x; v1.y = acc[mt][nt][3] + b2.y;
            if (EPI == 2 || EPI == 4){
                v0.x = gelu_t(v0.x); v0.y = gelu_t(v0.y);
                v1.x = gelu_t(v1.x); v1.y = gelu_t(v1.y);
            }
            size_t i0 = (size_t)row0*N + col, i1 = (size_t)(row0+8)*N + col;
            if (EPI == 3){
                float2 a0 = *(const float2*)(R1 + i0), a1 = *(const float2*)(R1 + i1);
                float2 x0 = *(const float2*)(R2 + i0), x1 = *(const float2*)(R2 + i1);
                v0.x += a0.x + x0.x; v0.y += a0.y + x0.y;
                v1.x += a1.x + x1.x; v1.y += a1.y + x1.y;
            }
            if (EPI == 4){
                float2 a0 = *(const float2*)(R1 + i0), a1 = *(const float2*)(R1 + i1);
                v0.x += a0.x; v0.y += a0.y;
                v1.x += a1.x; v1.y += a1.y;
            }
            if constexpr (sizeof(TC) == 2){
                *(__half2*)(C + i0) = __floats2half2_rn(v0.x, v0.y);
                *(__half2*)(C + i1) = __floats2half2_rn(v1.x, v1.y);
            } else {
                *(float2*)(C + i0) = v0;
                *(float2*)(C + i1) = v1;
            }
        }
    }
}

template<int EPI, typename TC>
__global__ void __launch_bounds__(256, 2)
hgemm_kernel(const __half* __restrict__ A, const __half* __restrict__ Bm,
             const float* __restrict__ bias, TC* __restrict__ C,
             const float* __restrict__ R1, const float* __restrict__ R2,
             int N, int K)
{
    hgemm_body<EPI, TC>(A, Bm, bias, C, R1, R2, N, K);
}

__global__ void __launch_bounds__(256, 2)
qkvr_kernel(int l)
{
    const int z = blockIdx.z;
    if (z == 3 && blockIdx.x*TBM >= S_) return;
    const __half* A = (z < 3) ? h_xn : h_rel;
    const __half* W = ((z==0) ? h_Wq : (z==1) ? h_Wk : (z==2) ? h_Wv : h_Wr) + (size_t)l*D_*D_;
    __half*       C = (z==0) ? h_q : (z==1) ? h_k : (z==2) ? h_v : h_r;
    hgemm_body<0, __half>(A, W, nullptr, C, nullptr, nullptr, D_, D_);
}

// ================= fp16 GEMM, TBN=64 variant =================================
#define TBN64 64
#define HG64_SMEM ((STAGES*TBM*40 + STAGES*TBK*72)*2)

template<int EPI, typename TC>
__global__ void __launch_bounds__(256, 2)
hgemm64_kernel(const __half* __restrict__ A, const __half* __restrict__ Bm,
               const float* __restrict__ bias, TC* __restrict__ C,
               const float* __restrict__ R1, const float* __restrict__ R2,
               int N, int K)
{
    extern __shared__ __half hsm[];
    __half* Asm = hsm;
    __half* Bsm = hsm + STAGES*TBM*40;

    const int tid = threadIdx.x;
    const int lane = tid & 31, wid = tid >> 5;
    const int wm = wid >> 1, wn = wid & 1;
    const int r = lane >> 2, cg = lane & 3;
    const int bm = blockIdx.x*TBM, bn = blockIdx.y*TBN64;

    const int arow = tid >> 1, ac0 = (tid & 1)*16;
    const int brow = tid >> 3, bc0 = (tid & 7)*8;

    const int aRowL = lane & 15, aKH = lane >> 4;
    const int bKL   = (lane & 7) + ((lane >> 3) & 1)*8, bNH = lane >> 4;

    float acc[2][4][4];
    #pragma unroll
    for (int mt=0;mt<2;mt++)
        #pragma unroll
        for (int nt=0;nt<4;nt++)
            #pragma unroll
            for (int i=0;i<4;i++) acc[mt][nt][i]=0.f;

    const int nkt = K/TBK;

    auto issue = [&](int kt, int s){
        __half* as = Asm + (s*TBM + arow)*40 + ac0;
        const __half* ap = A + (size_t)(bm+arow)*K + kt*TBK + ac0;
        cp16(as,   ap);
        cp16(as+8, ap+8);
        __half* bs = Bsm + (s*TBK + brow)*72 + bc0;
        const __half* bp = Bm + (size_t)(kt*TBK + brow)*N + bn + bc0;
        cp16(bs, bp);
    };

    #pragma unroll
    for (int s=0; s<STAGES-1; s++){ issue(s, s); CP_COMMIT(); }

    for (int kt=0; kt<nkt; kt++){
        CP_WAIT(STAGES-2);
        __syncthreads();
        const int nk = kt + STAGES-1;
        if (nk < nkt) issue(nk, nk & (STAGES-1));
        CP_COMMIT();

        const int s = kt & (STAGES-1);
        const __half* as = Asm + (size_t)s*TBM*40;
        const __half* bs = Bsm + (size_t)s*TBK*72;
        #pragma unroll
        for (int ks=0; ks<2; ks++){
            uint32_t af[2][4];
            #pragma unroll
            for (int mt=0;mt<2;mt++)
                ldsm_x4(af[mt], smaddr(as + (wm*32 + mt*16 + aRowL)*40 + ks*16 + aKH*8));
            #pragma unroll
            for (int nt=0;nt<2;nt++){
                uint32_t bf[4];
                ldsm_x4_t(bf, smaddr(bs + (ks*16 + bKL)*72 + wn*32 + nt*16 + bNH*8));
                mma_f16(acc[0][nt*2+0], af[0], bf[0], bf[1]);
                mma_f16(acc[1][nt*2+0], af[1], bf[0], bf[1]);
                mma_f16(acc[0][nt*2+1], af[0], bf[2], bf[3]);
                mma_f16(acc[1][nt*2+1], af[1], bf[2], bf[3]);
            }
        }
    }

    #pragma unroll
    for (int mt=0;mt<2;mt++){
        int row0 = bm + wm*32 + mt*16 + r;
        #pragma unroll
        for (int nt=0;nt<4;nt++){
            int col = bn + wn*32 + nt*8 + cg*2;
            float2 b2 = make_float2(0.f,0.f);
            if (EPI >= 1) b2 = *(const float2*)(bias + col);
            float2 v0, v1;
            v0.x = acc[mt][nt][0] + b2.x; v0.y = acc[mt][nt][1] + b2.y;
            v1.x = acc[mt][nt][2] + b2.x; v1.y = acc[mt][nt][3] + b2.y;
            if (EPI == 2 || EPI == 4){
                v0.x = gelu_t(v0.x); v0.y = gelu_t(v0.y);
                v1.x = gelu_t(v1.x); v1.y = gelu_t(v1.y);
            }
            size_t i0 = (size_t)row0*N + col, i1 = (size_t)(row0+8)*N + col;
            if (EPI == 3){
                float2 a0 = *(const float2*)(R1 + i0), a1 = *(const float2*)(R1 + i1);
                float2 x0 = *(const float2*)(R2 + i0), x1 = *(const float2*)(R2 + i1);
                v0.x += a0.x + x0.x; v0.y += a0.y + x0.y;
                v1.x += a1.x + x1.x; v1.y += a1.y + x1.y;
            }
            if (EPI == 4){
                float2 a0 = *(const float2*)(R1 + i0), a1 = *(const float2*)(R1 + i1);
                v0.x += a0.x; v0.y += a0.y;
                v1.x += a1.x; v1.y += a1.y;
            }
            if constexpr (sizeof(TC) == 2){
                *(__half2*)(C + i0) = __floats2half2_rn(v0.x, v0.y);
                *(__half2*)(C + i1) = __floats2half2_rn(v1.x, v1.y);
            } else {
                *(float2*)(C + i0) = v0;
                *(float2*)(C + i1) = v1;
            }
        }
    }
}

// ================= fused flash attention (R13 core + fused uk/vr) ============
#define FQH 72
#define FC2 132
#define FL_SMEM ((384*FQH)*2 + (64*FC2 + 128 + 128 + 64 + 64 + 64 + 64 + 64 + 128)*4)

__global__ void __launch_bounds__(256)
flash_kernel(const int* __restrict__ text,
             const float* __restrict__ uvec, const float* __restrict__ vvec){
    const int qtile = 15 - blockIdx.x;
    const int qt0 = qtile*64;
    const int bh = blockIdx.y, b = bh>>4, h = bh&15;

    extern __shared__ __half fsm[];
    __half* Qs = fsm;
    __half* Ks = Qs + 64*FQH;
    __half* Vs = Ks + 64*FQH;
    __half* Rs = Vs + 64*FQH;
    __half* Ps = Rs + 128*FQH;
    float*  C2  = (float*)(Ps + 64*FQH);
    float*  wmx = C2 + 64*FC2;
    float*  wsm = wmx + 128;
    float*  mrow = wsm + 128;
    float*  lrow = mrow + 64;
    float*  us   = lrow + 64;     // [64] u vector for head h
    float*  vs2  = us + 64;       // [64] v vector
    float*  uks  = vs2 + 64;      // [64] u·k per key in tile
    float*  vrs  = uks + 64;      // [128] v·r per band row

    const int tid = threadIdx.x;
    const int lane = tid&31, wid = tid>>5;
    const int wm = wid>>1, wn = wid&1;
    const int r = lane>>2, cg = lane&3;
    const int rowL = lane&15, kHalf = lane>>4;
    const int bKL = (lane&7) + ((lane>>3)&1)*8, bNH = lane>>4;

    {
        const int pos = tid>>2, c0 = (tid&3)*16;
        const __half* qp = h_q + ((size_t)(b*S_+qt0+pos))*D_ + h*DH_ + c0;
        *(uint4*)&Qs[pos*FQH+c0]   = *(const uint4*)qp;
        *(uint4*)&Qs[pos*FQH+c0+8] = *(const uint4*)(qp+8);
    }
    if (tid < 64){
        mrow[tid] = -1e30f; lrow[tid] = 0.f;
        us[tid]  = uvec[h*DH_ + tid];
        vs2[tid] = vvec[h*DH_ + tid];
    }

    float accO[4][4];
    #pragma unroll
    for (int nt=0;nt<4;nt++){ accO[nt][0]=accO[nt][1]=accO[nt][2]=accO[nt][3]=0.f; }

    for (int kt=0; kt<=qtile; kt++){
        __syncthreads();
        {
            const int pos = tid>>2, c0 = (tid&3)*16;
            const __half* kp = h_k + ((size_t)(b*S_+kt*64+pos))*D_ + h*DH_ + c0;
            *(uint4*)&Ks[pos*FQH+c0]   = *(const uint4*)kp;
            *(uint4*)&Ks[pos*FQH+c0+8] = *(const uint4*)(kp+8);
            const __half* vp = h_v + ((size_t)(b*S_+kt*64+pos))*D_ + h*DH_ + c0;
            *(uint4*)&Vs[pos*FQH+c0]   = *(const uint4*)vp;
            *(uint4*)&Vs[pos*FQH+c0+8] = *(const uint4*)(vp+8);
        }
        {
            const int rbase = S_ - 64 - qt0 + kt*64;
            const int j = tid>>1, rc0 = (tid&1)*32;
            const int rrow = rbase + j;
            if (rrow >= 0 && rrow < S_ && j < 127){
                const __half* rp = h_r + (size_t)rrow*D_ + h*DH_ + rc0;
                #pragma unroll
                for (int c=0;c<4;c++)
                    *(uint4*)&Rs[j*FQH + rc0 + c*8] = *(const uint4*)(rp + c*8);
            } else {
                uint4 z = make_uint4(0,0,0,0);
                #pragma unroll
                for (int c=0;c<4;c++)
                    *(uint4*)&Rs[j*FQH + rc0 + c*8] = z;
            }
        }
        __syncthreads();

        // ---- fused uk = u·K[kr], vr = v·R[j] (from smem tiles)
        {
            const int kr = tid>>2, d0 = (tid&3)*16;
            float p = 0.f;
            const __half* kp = Ks + kr*FQH + d0;
            #pragma unroll
            for (int c=0;c<8;c++){
                float2 f = __half22float2(*(const __half2*)(kp + c*2));
                p += f.x*us[d0+c*2] + f.y*us[d0+c*2+1];
            }
            p += __shfl_xor_sync(0xffffffffu, p, 1);
            p += __shfl_xor_sync(0xffffffffu, p, 2);
            if ((tid&3)==0) uks[kr] = p;
        }
        {
            const int j = tid>>1, d0 = (tid&1)*32;
            float p = 0.f;
            const __half* rp = Rs + j*FQH + d0;
            #pragma unroll
            for (int c=0;c<16;c++){
                float2 f = __half22float2(*(const __half2*)(rp + c*2));
                p += f.x*vs2[d0+c*2] + f.y*vs2[d0+c*2+1];
            }
            p += __shfl_xor_sync(0xffffffffu, p, 1);
            if ((tid&1)==0) vrs[j] = p;
        }

        float accA[4][4], accB[8][4];
        #pragma unroll
        for (int nt=0;nt<4;nt++){ accA[nt][0]=accA[nt][1]=accA[nt][2]=accA[nt][3]=0.f; }
        #pragma unroll
        for (int nt=0;nt<8;nt++){ accB[nt][0]=accB[nt][1]=accB[nt][2]=accB[nt][3]=0.f; }
        #pragma unroll
        for (int ks=0; ks<4; ks++){
            uint32_t a[4];
            ldsm_x4(a, smaddr(Qs + (wm*16 + rowL)*FQH + ks*16 + kHalf*8));
            #pragma unroll
            for (int np=0; np<2; np++){
                uint32_t bk[4];
                ldsm_x4(bk, smaddr(Ks + (wn*32 + np*16 + rowL)*FQH + ks*16 + kHalf*8));
                mma_f16(accA[np*2+0], a, bk[0], bk[2]);
                mma_f16(accA[np*2+1], a, bk[1], bk[3]);
            }
            #pragma unroll
            for (int np=0; np<4; np++){
                uint32_t br[4];
                ldsm_x4(br, smaddr(Rs + (wn*64 + np*16 + rowL)*FQH + ks*16 + kHalf*8));
                mma_f16(accB[np*2+0], a, br[0], br[2]);
                mma_f16(accB[np*2+1], a, br[1], br[3]);
            }
        }
        #pragma unroll
        for (int nt=0;nt<8;nt++){
            int col = wn*64 + nt*8 + cg*2;
            C2[(wm*16+r  )*FC2 + col    ] = accB[nt][0];
            C2[(wm*16+r  )*FC2 + col + 1] = accB[nt][1];
            C2[(wm*16+r+8)*FC2 + col    ] = accB[nt][2];
            C2[(wm*16+r+8)*FC2 + col + 1] = accB[nt][3];
        }
        __syncthreads();

        float sv[2][4][2];
        float tmax[2] = {-1e30f, -1e30f};
        #pragma unroll
        for (int i=0;i<2;i++){
            const int qr = wm*16 + r + i*8;
            const int q  = qt0 + qr;
            #pragma unroll
            for (int nt=0;nt<4;nt++){
                #pragma unroll
                for (int cc=0;cc<2;cc++){
                    const int kr = wn*32 + nt*8 + cg*2 + cc;
                    const int k  = kt*64 + kr;
                    float v;
                    if (k <= q){
                        const int jj = 63 + kr - qr;
                        v = (accA[nt][i*2+cc] + uks[kr]
                             + C2[qr*FC2 + jj] + vrs[jj]) * 0.125f;
                    } else v = -1e30f;
                    sv[i][nt][cc] = v;
                    tmax[i] = fmaxf(tmax[i], v);
                }
            }
        }
        #pragma unroll
        for (int i=0;i<2;i++){
            tmax[i] = fmaxf(tmax[i], __shfl_xor_sync(0xffffffffu, tmax[i], 1));
            tmax[i] = fmaxf(tmax[i], __shfl_xor_sync(0xffffffffu, tmax[i], 2));
        }
        if (cg == 0){
            wmx[wn*64 + wm*16 + r    ] = tmax[0];
            wmx[wn*64 + wm*16 + r + 8] = tmax[1];
        }
        __syncthreads();

        #pragma unroll
        for (int i=0;i<2;i++){
            const int row = wm*16 + r + i*8;
            float m_old = mrow[row];
            float m_new = fmaxf(m_old, fmaxf(wmx[row], wmx[64+row]));
            float scl = __expf(m_old - m_new);
            float psum = 0.f;
            #pragma unroll
            for (int nt=0;nt<4;nt++){
                float p0 = __expf(sv[i][nt][0] - m_new);
                float p1 = __expf(sv[i][nt][1] - m_new);
                psum += p0 + p1;
                *(__half2*)&Ps[row*FQH + wn*32 + nt*8 + cg*2] = __floats2half2_rn(p0, p1);
                accO[nt][i*2+0] *= scl;
                accO[nt][i*2+1] *= scl;
            }
            psum += __shfl_xor_sync(0xffffffffu, psum, 1);
            psum += __shfl_xor_sync(0xffffffffu, psum, 2);
            if (cg == 0) wsm[wn*64 + row] = psum;
        }
        __syncthreads();

        if (tid < 64){
            float m_old = mrow[tid];
            float m_new = fmaxf(m_old, fmaxf(wmx[tid], wmx[64+tid]));
            lrow[tid] = lrow[tid]*__expf(m_old - m_new) + wsm[tid] + wsm[64+tid];
            mrow[tid] = m_new;
        }
        #pragma unroll
        for (int ks=0; ks<4; ks++){
            uint32_t af[4];
            ldsm_x4(af, smaddr(Ps + (wm*16 + rowL)*FQH + ks*16 + kHalf*8));
            #pragma unroll
            for (int nt=0; nt<2; nt++){
                uint32_t bf[4];
                ldsm_x4_t(bf, smaddr(Vs + (ks*16 + bKL)*FQH + wn*32 + nt*16 + bNH*8));
                mma_f16(accO[nt*2+0], af, bf[0], bf[1]);
                mma_f16(accO[nt*2+1], af, bf[2], bf[3]);
            }
        }
    }
    __syncthreads();

    #pragma unroll
    for (int i=0;i<2;i++){
        const int row = wm*16 + r + i*8;
        const int q   = qt0 + row;
        bool padq = (text[b*CTX_ + q] == PAD_);
        float inv = padq ? 0.f : 1.0f/lrow[row];
        #pragma unroll
        for (int nt=0;nt<4;nt++){
            int col = h*DH_ + wn*32 + nt*8 + cg*2;
            __half2 o2 = __floats2half2_rn(accO[nt][i*2+0]*inv, accO[nt][i*2+1]*inv);
            *(__half2*)(h_o + (size_t)(b*S_ + q)*D_ + col) = o2;
        }
    }
}

// ---------------- orchestration -----------------------------------------------
extern "C" void kernel_launch(void* const* d_in, const int* in_sizes, int n_in,
                              void* d_out, int out_size)
{
    (void)in_sizes; (void)n_in; (void)out_size;
    const int*   text = (const int*)  d_in[0];
    const float* emb  = (const float*)d_in[1];
    const float* u    = (const float*)d_in[2];
    const float* vbp  = (const float*)d_in[3];
    const float* Wq   = (const float*)d_in[4];
    const float* Wk   = (const float*)d_in[5];
    const float* Wv   = (const float*)d_in[6];
    const float* Wr   = (const float*)d_in[7];
    const float* Wfc  = (const float*)d_in[8];
    const float* bfc  = (const float*)d_in[9];
    const float* ln1g = (const float*)d_in[10];
    const float* ln1b = (const float*)d_in[11];
    const float* ln2g = (const float*)d_in[12];
    const float* ln2b = (const float*)d_in[13];
    const float* W1   = (const float*)d_in[14];
    const float* b1   = (const float*)d_in[15];
    const float* W2   = (const float*)d_in[16];
    const float* b2   = (const float*)d_in[17];
    const float* lnfg = (const float*)d_in[18];
    const float* lnfb = (const float*)d_in[19];
    const float* Wlm  = (const float*)d_in[20];
    const float* blm  = (const float*)d_in[21];
    float* out = (float*)d_out;

    float *px,*pxn;
    __half *pWq16,*pWk16,*pWv16,*pWr16,*pWfc16,*pW116,*pW216,*pWlm16,*pxn16,*po16,*pff16;
    cudaGetSymbolAddress((void**)&px,   g_x);
    cudaGetSymbolAddress((void**)&pxn,  g_xn);
    cudaGetSymbolAddress((void**)&pWq16, h_Wq);
    cudaGetSymbolAddress((void**)&pWk16, h_Wk);
    cudaGetSymbolAddress((void**)&pWv16, h_Wv);
    cudaGetSymbolAddress((void**)&pWr16, h_Wr);
    cudaGetSymbolAddress((void**)&pWfc16,h_Wfc);
    cudaGetSymbolAddress((void**)&pW116, h_W1);
    cudaGetSymbolAddress((void**)&pW216, h_W2);
    cudaGetSymbolAddress((void**)&pWlm16,h_Wlm);
    cudaGetSymbolAddress((void**)&pxn16, h_xn);
    cudaGetSymbolAddress((void**)&po16,  h_o);
    cudaGetSymbolAddress((void**)&pff16, h_ff);

    static bool attr_done = false;
    if (!attr_done){
        cudaFuncSetAttribute(flash_kernel, cudaFuncAttributeMaxDynamicSharedMemorySize, FL_SMEM);
        cudaFuncSetAttribute(qkvr_kernel,  cudaFuncAttributeMaxDynamicSharedMemorySize, HG_SMEM);
        cudaFuncSetAttribute((const void*)hgemm_kernel<1,float>,    cudaFuncAttributeMaxDynamicSharedMemorySize, HG_SMEM);
        cudaFuncSetAttribute((const void*)hgemm_kernel<2,__half>,   cudaFuncAttributeMaxDynamicSharedMemorySize, HG_SMEM);
        cudaFuncSetAttribute((const void*)hgemm64_kernel<3,float>,  cudaFuncAttributeMaxDynamicSharedMemorySize, HG64_SMEM);
        cudaFuncSetAttribute((const void*)hgemm64_kernel<4,float>,  cudaFuncAttributeMaxDynamicSharedMemorySize, HG64_SMEM);
        attr_done = true;
    }

    const int MR = B_*S_;

    // ---- merged fp32 -> fp16 weight conversion (one launch) -----------------
    cvt_all_kernel<<<N8_TOTAL/256, 256>>>(
        (const float4*)Wq,  (const float4*)Wk,  (const float4*)Wv,  (const float4*)Wr,
        (const float4*)Wfc, (const float4*)W1,  (const float4*)W2,  (const float4*)Wlm);

    embed_kernel<<<2048,256>>>(text, emb);
    rel_kernel  <<<2048,256>>>();

    for (int l=0; l<L_; l++){
        ln_kernel<<<MR,256>>>(px, pxn, pxn16, ln1g + l*D_, ln1b + l*D_, 1);

        qkvr_kernel<<<dim3(MR/TBM, D_/TBN, 4),256, HG_SMEM>>>(l);

        flash_kernel<<<dim3(16, B_*H_),256, FL_SMEM>>>(text, u, vbp);

        // x = x + xn + o@Wfc + bfc
        hgemm64_kernel<3,float><<<dim3(MR/TBM, D_/TBN64),256, HG64_SMEM>>>(
            po16, pWfc16 + (size_t)l*D_*D_, bfc + l*D_, px, px, pxn, D_, D_);

        ln_kernel<<<MR,256>>>(px, pxn, pxn16, ln2g + l*D_, ln2b + l*D_, 0);
        hgemm_kernel<2,__half><<<dim3(MR/TBM, FF_/TBN),256, HG_SMEM>>>(
            pxn16, pW116 + (size_t)l*D_*FF_, b1 + l*FF_, pff16, nullptr, nullptr, FF_, D_);
        // x = x + gelu(ff@W2 + b2)
        hgemm64_kernel<4,float><<<dim3(MR/TBM, D_/TBN64),256, HG64_SMEM>>>(
            pff16, pW216 + (size_t)l*FF_*D_, b2 + l*D_, px, px, nullptr, D_, FF_);
    }

    ln_kernel<<<MR,256>>>(px, pxn, pxn16, lnfg, lnfb, 0);
    hgemm_kernel<1,float><<<dim3(MR/TBM, V_/TBN),256, HG_SMEM>>>(
        pxn16, pWlm16, blm, out, nullptr, nullptr, V_, D_);
}

// round 16
// speedup vs baseline: 1.0181x; 1.0181x over previous
#include <cuda_runtime.h>
#include <cuda_fp16.h>
#include <stdint.h>
#include <math.h>

#define B_   2
#define S_   1024
#define D_   1024
#define H_   16
#define DH_  64
#define FF_  4096
#define V_   32000
#define L_   4
#define PAD_ 3
#define CTX_ 1025

// ---------------- scratch (fp32) ----------------------------------------------
__device__ float g_x  [B_*S_*D_];
__device__ float g_xn [B_*S_*D_];
__device__ float g_uk [B_*H_*S_];
__device__ float g_vr [H_*S_];

// ---------------- fp16 weights + activations -----------------------------------
__device__ __align__(16) __half h_Wq [L_*D_*D_];
__device__ __align__(16) __half h_Wk [L_*D_*D_];
__device__ __align__(16) __half h_Wv [L_*D_*D_];
__device__ __align__(16) __half h_Wr [L_*D_*D_];
__device__ __align__(16) __half h_Wfc[L_*D_*D_];
__device__ __align__(16) __half h_W1 [L_*D_*FF_];
__device__ __align__(16) __half h_W2 [L_*FF_*D_];
__device__ __align__(16) __half h_Wlm[(size_t)D_*V_];
__device__ __align__(16) __half h_xn [B_*S_*D_];
__device__ __align__(16) __half h_rel[S_*D_];
__device__ __align__(16) __half h_o  [B_*S_*D_];
__device__ __align__(16) __half h_ff [B_*S_*FF_];
__device__ __align__(16) __half h_q  [B_*S_*D_];
__device__ __align__(16) __half h_k  [B_*S_*D_];
__device__ __align__(16) __half h_v  [B_*S_*D_];
__device__ __align__(16) __half h_r  [S_*D_];

// ---------------- helpers --------------------------------------------------
__device__ __forceinline__ float gelu_t(float x){
    return 0.5f*x*(1.0f + tanhf(0.7978845608028654f*(x + 0.044715f*x*x*x)));
}
__device__ __forceinline__ uint32_t smaddr(const void* p){
    return (uint32_t)__cvta_generic_to_shared(p);
}
__device__ __forceinline__ void cp16(void* smem, const void* gmem){
    asm volatile("cp.async.cg.shared.global [%0], [%1], 16;\n"
        :: "r"(smaddr(smem)), "l"(gmem));
}
#define CP_COMMIT() asm volatile("cp.async.commit_group;\n" ::: "memory")
#define CP_WAIT(N)  asm volatile("cp.async.wait_group %0;\n" :: "n"(N) : "memory")

__device__ __forceinline__ void mma_f16(float c[4], const uint32_t a[4], const uint32_t b0, const uint32_t b1){
    asm volatile(
      "mma.sync.aligned.m16n8k16.row.col.f32.f16.f16.f32 "
      "{%0,%1,%2,%3}, {%4,%5,%6,%7}, {%8,%9}, {%0,%1,%2,%3};\n"
      : "+f"(c[0]), "+f"(c[1]), "+f"(c[2]), "+f"(c[3])
      : "r"(a[0]), "r"(a[1]), "r"(a[2]), "r"(a[3]), "r"(b0), "r"(b1));
}
__device__ __forceinline__ void ldsm_x4(uint32_t r[4], uint32_t addr){
    asm volatile("ldmatrix.sync.aligned.m8n8.x4.shared.b16 {%0,%1,%2,%3}, [%4];"
      : "=r"(r[0]), "=r"(r[1]), "=r"(r[2]), "=r"(r[3]) : "r"(addr));
}
__device__ __forceinline__ void ldsm_x4_t(uint32_t r[4], uint32_t addr){
    asm volatile("ldmatrix.sync.aligned.m8n8.x4.trans.shared.b16 {%0,%1,%2,%3}, [%4];"
      : "=r"(r[0]), "=r"(r[1]), "=r"(r[2]), "=r"(r[3]) : "r"(addr));
}

// ---------------- merged fp32 -> fp16 weight convert -------------------------
#define N8_DD (L_*D_*D_/8)
#define N8_DF (L_*D_*FF_/8)
#define N8_LM (D_*V_/8)
#define N8_TOTAL (5*N8_DD + 2*N8_DF + N8_LM)

__global__ void cvt_all_kernel(
    const float4* __restrict__ Wq,  const float4* __restrict__ Wk,
    const float4* __restrict__ Wv,  const float4* __restrict__ Wr,
    const float4* __restrict__ Wfc, const float4* __restrict__ W1,
    const float4* __restrict__ W2,  const float4* __restrict__ Wlm)
{
    int i = blockIdx.x*256 + threadIdx.x;
    const float4* src; uint4* dst; size_t j;
    if (i < 5*N8_DD){
        int t = i / N8_DD; j = i - t*N8_DD;
        src = (t==0)?Wq:(t==1)?Wk:(t==2)?Wv:(t==3)?Wr:Wfc;
        dst = (t==0)?(uint4*)h_Wq:(t==1)?(uint4*)h_Wk:(t==2)?(uint4*)h_Wv:(t==3)?(uint4*)h_Wr:(uint4*)h_Wfc;
    } else if (i < 5*N8_DD + 2*N8_DF){
        int k = i - 5*N8_DD; int t = k / N8_DF; j = k - t*N8_DF;
        src = t ? W2 : W1;
        dst = t ? (uint4*)h_W2 : (uint4*)h_W1;
    } else {
        j = i - (5*N8_DD + 2*N8_DF);
        src = Wlm; dst = (uint4*)h_Wlm;
    }
    float4 a = src[j*2], b = src[j*2+1];
    __half2 h0 = __floats2half2_rn(a.x, a.y);
    __half2 h1 = __floats2half2_rn(a.z, a.w);
    __half2 h2 = __floats2half2_rn(b.x, b.y);
    __half2 h3 = __floats2half2_rn(b.z, b.w);
    dst[j] = make_uint4(*(uint32_t*)&h0, *(uint32_t*)&h1, *(uint32_t*)&h2, *(uint32_t*)&h3);
}

// ---------------- embedding ------------------------------------------------
__global__ void embed_kernel(const int* __restrict__ text, const float* __restrict__ emb){
    int idx = blockIdx.x*256 + threadIdx.x;
    int d4  = idx & (D_/4 - 1);
    int bs  = idx >> 8;
    int s   = bs & (S_-1);
    int b   = bs >> 10;
    int tok = text[b*CTX_ + s];
    ((float4*)g_x)[idx] = ((const float4*)(emb + (size_t)tok*D_))[d4];
}

// ---------------- sinusoidal relative positions (fp16 out) ------------------
__global__ void rel_kernel(){
    int idx = blockIdx.x*256 + threadIdx.x;
    int j = idx & 511;
    int s = idx >> 9;
    float pos  = (float)(S_-1-s);
    float invf = powf(10000.0f, -(float)(2*j)/(float)D_);
    float a = pos*invf;
    h_rel[s*D_ + j]       = __float2half_rn(sinf(a));
    h_rel[s*D_ + j + 512] = __float2half_rn(cosf(a));
}

// ---------------- layernorm (fp16 out; optional fp32 out) --------------------
__global__ void ln_kernel(const float* __restrict__ in, float* __restrict__ out,
                          __half* __restrict__ out16,
                          const float* __restrict__ gam, const float* __restrict__ bet,
                          int write32){
    int row = blockIdx.x;
    int t = threadIdx.x;
    const float4* x4 = (const float4*)(in + (size_t)row*D_);
    float4 v = x4[t];
    float s  = v.x+v.y+v.z+v.w;
    float s2 = v.x*v.x+v.y*v.y+v.z*v.z+v.w*v.w;
    #pragma unroll
    for (int o=16;o;o>>=1){ s += __shfl_xor_sync(0xffffffffu,s,o); s2 += __shfl_xor_sync(0xffffffffu,s2,o); }
    __shared__ float shs[8], shs2[8], bc[2];
    int w = t>>5, lane = t&31;
    if (!lane){ shs[w]=s; shs2[w]=s2; }
    __syncthreads();
    if (t==0){
        float ts=0.f, ts2=0.f;
        #pragma unroll
        for (int i=0;i<8;i++){ ts+=shs[i]; ts2+=shs2[i]; }
        float m   = ts*(1.0f/(float)D_);
        float var = ts2*(1.0f/(float)D_) - m*m;
        bc[0]=m; bc[1]=rsqrtf(var + 1e-5f);
    }
    __syncthreads();
    float m = bc[0], inv = bc[1];
    float4 gg = ((const float4*)gam)[t];
    float4 bb = ((const float4*)bet)[t];
    float4 o4;
    o4.x = (v.x-m)*inv*gg.x + bb.x;
    o4.y = (v.y-m)*inv*gg.y + bb.y;
    o4.z = (v.z-m)*inv*gg.z + bb.z;
    o4.w = (v.w-m)*inv*gg.w + bb.w;
    if (write32)
        ((float4*)(out + (size_t)row*D_))[t] = o4;
    __half2 p0 = __floats2half2_rn(o4.x, o4.y);
    __half2 p1 = __floats2half2_rn(o4.z, o4.w);
    *(uint2*)(out16 + (size_t)row*D_ + t*4) = make_uint2(*(uint32_t*)&p0, *(uint32_t*)&p1);
}

// ================= fp16 GEMM with cp.async 5-stage pipeline ==================
#define TBM 128
#define TBN 128
#define TBK 32
#define STAGES 5
#define HG_SMEM ((STAGES*TBM*40 + STAGES*TBK*136)*2)

// EPI: 0 plain | 1 +bias | 2 gelu(acc+bias) | 3 R1+R2+acc+bias | 4 R1+gelu(acc+bias)
template<int EPI, typename TC>
__device__ __forceinline__ void hgemm_body(
    const __half* __restrict__ A, const __half* __restrict__ Bm,
    const float* __restrict__ bias, TC* __restrict__ C,
    const float* __restrict__ R1, const float* __restrict__ R2,
    int N, int K)
{
    extern __shared__ __half hsm[];
    __half* Asm = hsm;
    __half* Bsm = hsm + STAGES*TBM*40;

    const int tid = threadIdx.x;
    const int lane = tid & 31, wid = tid >> 5;
    const int wm = wid >> 1, wn = wid & 1;
    const int r = lane >> 2, cg = lane & 3;
    const int bm = blockIdx.x*TBM, bn = blockIdx.y*TBN;

    const int arow = tid >> 1, ac0 = (tid & 1)*16;
    const int brow = tid >> 3, bc0 = (tid & 7)*16;

    const int aRowL = lane & 15, aKH = lane >> 4;
    const int bKL   = (lane & 7) + ((lane >> 3) & 1)*8, bNH = lane >> 4;

    float acc[2][8][4];
    #pragma unroll
    for (int mt=0;mt<2;mt++)
        #pragma unroll
        for (int nt=0;nt<8;nt++)
            #pragma unroll
            for (int i=0;i<4;i++) acc[mt][nt][i]=0.f;

    const int nkt = K/TBK;

    auto issue = [&](int kt, int s){
        __half* as = Asm + (s*TBM + arow)*40 + ac0;
        const __half* ap = A + (size_t)(bm+arow)*K + kt*TBK + ac0;
        cp16(as,   ap);
        cp16(as+8, ap+8);
        __half* bs = Bsm + (s*TBK + brow)*136 + bc0;
        const __half* bp = Bm + (size_t)(kt*TBK + brow)*N + bn + bc0;
        cp16(bs,   bp);
        cp16(bs+8, bp+8);
    };

    #pragma unroll
    for (int s=0; s<STAGES-1; s++){ issue(s, s); CP_COMMIT(); }

    for (int kt=0; kt<nkt; kt++){
        CP_WAIT(STAGES-2);
        __syncthreads();
        const int nk = kt + STAGES-1;
        if (nk < nkt) issue(nk, nk % STAGES);
        CP_COMMIT();

        const int s = kt % STAGES;
        const __half* as = Asm + (size_t)s*TBM*40;
        const __half* bs = Bsm + (size_t)s*TBK*136;
        #pragma unroll
        for (int ks=0; ks<2; ks++){
            uint32_t af[2][4];
            #pragma unroll
            for (int mt=0;mt<2;mt++)
                ldsm_x4(af[mt], smaddr(as + (wm*32 + mt*16 + aRowL)*40 + ks*16 + aKH*8));
            #pragma unroll
            for (int nt=0;nt<4;nt++){
                uint32_t bf[4];
                ldsm_x4_t(bf, smaddr(bs + (ks*16 + bKL)*136 + wn*64 + nt*16 + bNH*8));
                mma_f16(acc[0][nt*2+0], af[0], bf[0], bf[1]);
                mma_f16(acc[1][nt*2+0], af[1], bf[0], bf[1]);
                mma_f16(acc[0][nt*2+1], af[0], bf[2], bf[3]);
                mma_f16(acc[1][nt*2+1], af[1], bf[2], bf[3]);
            }
        }
    }

    #pragma unroll
    for (int mt=0;mt<2;mt++){
        int row0 = bm + wm*32 + mt*16 + r;
        #pragma unroll
        for (int nt=0;nt<8;nt++){
            int col = bn + wn*64 + nt*8 + cg*2;
            float2 b2 = make_float2(0.f,0.f);
            if (EPI >= 1) b2 = *(const float2*)(bias + col);
            float2 v0, v1;
            v0.x = acc[mt][nt][0] + b2.x; v0.y = acc[mt][nt][1] + b2.y;
            v1.x = acc[mt][nt][2] + b2.x; v1.y = acc[mt][nt][3] + b2.y;
            if (EPI == 2 || EPI == 4){
                v0.x = gelu_t(v0.x); v0.y = gelu_t(v0.y);
                v1.x = gelu_t(v1.x); v1.y = gelu_t(v1.y);
            }
            size_t i0 = (size_t)row0*N + col, i1 = (size_t)(row0+8)*N + col;
            if (EPI == 3){
                float2 a0 = *(const float2*)(R1 + i0), a1 = *(const float2*)(R1 + i1);
                float2 x0 = *(const float2*)(R2 + i0), x1 = *(const float2*)(R2 + i1);
                v0.x += a0.x + x0.x; v0.y += a0.y + x0.y;
                v1.x += a1.x + x1.x; v1.y += a1.y + x1.y;
            }
            if (EPI == 4){
                float2 a0 = *(const float2*)(R1 + i0), a1 = *(const float2*)(R1 + i1);
                v0.x += a0.x; v0.y += a0.y;
                v1.x += a1.x; v1.y += a1.y;
            }
            if constexpr (sizeof(TC) == 2){
                *(__half2*)(C + i0) = __floats2half2_rn(v0.x, v0.y);
                *(__half2*)(C + i1) = __floats2half2_rn(v1.x, v1.y);
            } else {
                *(float2*)(C + i0) = v0;
                *(float2*)(C + i1) = v1;
            }
        }
    }
}

template<int EPI, typename TC>
__global__ void __launch_bounds__(256, 2)
hgemm_kernel(const __half* __restrict__ A, const __half* __restrict__ Bm,
             const float* __restrict__ bias, TC* __restrict__ C,
             const float* __restrict__ R1, const float* __restrict__ R2,
             int N, int K)
{
    hgemm_body<EPI, TC>(A, Bm, bias, C, R1, R2, N, K);
}

__global__ void __launch_bounds__(256, 2)
qkvr_kernel(int l)
{
    const int z = blockIdx.z;
    if (z == 3 && blockIdx.x*TBM >= S_) return;
    const __half* A = (z < 3) ? h_xn : h_rel;
    const __half* W = ((z==0) ? h_Wq : (z==1) ? h_Wk : (z==2) ? h_Wv : h_Wr) + (size_t)l*D_*D_;
    __half*       C = (z==0) ? h_q : (z==1) ? h_k : (z==2) ? h_v : h_r;
    hgemm_body<0, __half>(A, W, nullptr, C, nullptr, nullptr, D_, D_);
}

// ---------------- bias precompute: uk[b,h,key]=u·k, vr[h,row]=v·r ----------
__global__ void bias_kernel(const float* __restrict__ uvec, const float* __restrict__ vvec){
    const int t = threadIdx.x;
    float4 uu;
    float2 f0, f1;
    if (blockIdx.y == 0){
        int row = blockIdx.x;
        uint2 raw = *(const uint2*)(h_k + (size_t)row*D_ + t*4);
        f0 = __half22float2(*(__half2*)&raw.x);
        f1 = __half22float2(*(__half2*)&raw.y);
        uu = ((const float4*)uvec)[t];
        float p = f0.x*uu.x + f0.y*uu.y + f1.x*uu.z + f1.y*uu.w;
        p += __shfl_xor_sync(0xffffffffu, p, 8);
        p += __shfl_xor_sync(0xffffffffu, p, 4);
        p += __shfl_xor_sync(0xffffffffu, p, 2);
        p += __shfl_xor_sync(0xffffffffu, p, 1);
        if ((t & 15) == 0){
            int h = t >> 4;
            int b = row >> 10, key = row & (S_-1);
            g_uk[((size_t)(b*H_ + h))*S_ + key] = p;
        }
    } else {
        int rrow = blockIdx.x;
        if (rrow >= S_) return;
        uint2 raw = *(const uint2*)(h_r + (size_t)rrow*D_ + t*4);
        f0 = __half22float2(*(__half2*)&raw.x);
        f1 = __half22float2(*(__half2*)&raw.y);
        uu = ((const float4*)vvec)[t];
        float p = f0.x*uu.x + f0.y*uu.y + f1.x*uu.z + f1.y*uu.w;
        p += __shfl_xor_sync(0xffffffffu, p, 8);
        p += __shfl_xor_sync(0xffffffffu, p, 4);
        p += __shfl_xor_sync(0xffffffffu, p, 2);
        p += __shfl_xor_sync(0xffffffffu, p, 1);
        if ((t & 15) == 0)
            g_vr[(t>>4)*S_ + rrow] = p;
    }
}

// ================= fused flash attention (R11-exact) =========================
#define FQH 72
#define FC2 132
#define FL_SMEM ((384*FQH)*2 + (64*FC2 + 128 + 128 + 64 + 64)*4)

__global__ void __launch_bounds__(256)
flash_kernel(const int* __restrict__ text){
    const int qtile = 15 - blockIdx.x;
    const int qt0 = qtile*64;
    const int bh = blockIdx.y, b = bh>>4, h = bh&15;

    extern __shared__ __half fsm[];
    __half* Qs = fsm;
    __half* Ks = Qs + 64*FQH;
    __half* Vs = Ks + 64*FQH;
    __half* Rs = Vs + 64*FQH;
    __half* Ps = Rs + 128*FQH;
    float*  C2  = (float*)(Ps + 64*FQH);
    float*  wmx = C2 + 64*FC2;
    float*  wsm = wmx + 128;
    float*  mrow = wsm + 128;
    float*  lrow = mrow + 64;

    const int tid = threadIdx.x;
    const int lane = tid&31, wid = tid>>5;
    const int wm = wid>>1, wn = wid&1;
    const int r = lane>>2, cg = lane&3;
    const int rowL = lane&15, kHalf = lane>>4;
    const int bKL = (lane&7) + ((lane>>3)&1)*8, bNH = lane>>4;

    {
        const int pos = tid>>2, c0 = (tid&3)*16;
        const __half* qp = h_q + ((size_t)(b*S_+qt0+pos))*D_ + h*DH_ + c0;
        *(uint4*)&Qs[pos*FQH+c0]   = *(const uint4*)qp;
        *(uint4*)&Qs[pos*FQH+c0+8] = *(const uint4*)(qp+8);
    }
    if (tid < 64){ mrow[tid] = -1e30f; lrow[tid] = 0.f; }

    float accO[4][4];
    #pragma unroll
    for (int nt=0;nt<4;nt++){ accO[nt][0]=accO[nt][1]=accO[nt][2]=accO[nt][3]=0.f; }

    const float* ukb = g_uk + (size_t)bh*S_;
    const float* vrp = g_vr + (size_t)h*S_;

    for (int kt=0; kt<=qtile; kt++){
        __syncthreads();
        {
            const int pos = tid>>2, c0 = (tid&3)*16;
            const __half* kp = h_k + ((size_t)(b*S_+kt*64+pos))*D_ + h*DH_ + c0;
            *(uint4*)&Ks[pos*FQH+c0]   = *(const uint4*)kp;
            *(uint4*)&Ks[pos*FQH+c0+8] = *(const uint4*)(kp+8);
            const __half* vp = h_v + ((size_t)(b*S_+kt*64+pos))*D_ + h*DH_ + c0;
            *(uint4*)&Vs[pos*FQH+c0]   = *(const uint4*)vp;
            *(uint4*)&Vs[pos*FQH+c0+8] = *(const uint4*)(vp+8);
        }
        {
            const int rbase = S_ - 64 - qt0 + kt*64;
            const int j = tid>>1, rc0 = (tid&1)*32;
            const int rrow = rbase + j;
            if (rrow >= 0 && rrow < S_ && j < 127){
                const __half* rp = h_r + (size_t)rrow*D_ + h*DH_ + rc0;
                #pragma unroll
                for (int c=0;c<4;c++)
                    *(uint4*)&Rs[j*FQH + rc0 + c*8] = *(const uint4*)(rp + c*8);
            } else {
                uint4 z = make_uint4(0,0,0,0);
                #pragma unroll
                for (int c=0;c<4;c++)
                    *(uint4*)&Rs[j*FQH + rc0 + c*8] = z;
            }
        }
        __syncthreads();

        float accA[4][4], accB[8][4];
        #pragma unroll
        for (int nt=0;nt<4;nt++){ accA[nt][0]=accA[nt][1]=accA[nt][2]=accA[nt][3]=0.f; }
        #pragma unroll
        for (int nt=0;nt<8;nt++){ accB[nt][0]=accB[nt][1]=accB[nt][2]=accB[nt][3]=0.f; }
        #pragma unroll
        for (int ks=0; ks<4; ks++){
            uint32_t a[4];
            ldsm_x4(a, smaddr(Qs + (wm*16 + rowL)*FQH + ks*16 + kHalf*8));
            #pragma unroll
            for (int np=0; np<2; np++){
                uint32_t bk[4];
                ldsm_x4(bk, smaddr(Ks + (wn*32 + np*16 + rowL)*FQH + ks*16 + kHalf*8));
                mma_f16(accA[np*2+0], a, bk[0], bk[2]);
                mma_f16(accA[np*2+1], a, bk[1], bk[3]);
            }
            #pragma unroll
            for (int np=0; np<4; np++){
                uint32_t br[4];
                ldsm_x4(br, smaddr(Rs + (wn*64 + np*16 + rowL)*FQH + ks*16 + kHalf*8));
                mma_f16(accB[np*2+0], a, br[0], br[2]);
                mma_f16(accB[np*2+1], a, br[1], br[3]);
            }
        }
        #pragma unroll
        for (int nt=0;nt<8;nt++){
            int col = wn*64 + nt*8 + cg*2;
            C2[(wm*16+r  )*FC2 + col    ] = accB[nt][0];
            C2[(wm*16+r  )*FC2 + col + 1] = accB[nt][1];
            C2[(wm*16+r+8)*FC2 + col    ] = accB[nt][2];
            C2[(wm*16+r+8)*FC2 + col + 1] = accB[nt][3];
        }
        __syncthreads();

        const float* ukp = ukb + kt*64;
        float sv[2][4][2];
        float tmax[2] = {-1e30f, -1e30f};
        #pragma unroll
        for (int i=0;i<2;i++){
            const int qr = wm*16 + r + i*8;
            const int q  = qt0 + qr;
            #pragma unroll
            for (int nt=0;nt<4;nt++){
                #pragma unroll
                for (int cc=0;cc<2;cc++){
                    const int kr = wn*32 + nt*8 + cg*2 + cc;
                    const int k  = kt*64 + kr;
                    float v;
                    if (k <= q){
                        v = (accA[nt][i*2+cc] + ukp[kr]
                             + C2[qr*FC2 + 63 + kr - qr] + vrp[S_-1-q+k]) * 0.125f;
                    } else v = -1e30f;
                    sv[i][nt][cc] = v;
                    tmax[i] = fmaxf(tmax[i], v);
                }
            }
        }
        #pragma unroll
        for (int i=0;i<2;i++){
            tmax[i] = fmaxf(tmax[i], __shfl_xor_sync(0xffffffffu, tmax[i], 1));
            tmax[i] = fmaxf(tmax[i], __shfl_xor_sync(0xffffffffu, tmax[i], 2));
        }
        if (cg == 0){
            wmx[wn*64 + wm*16 + r    ] = tmax[0];
            wmx[wn*64 + wm*16 + r + 8] = tmax[1];
        }
        __syncthreads();

        #pragma unroll
        for (int i=0;i<2;i++){
            const int row = wm*16 + r + i*8;
            float m_old = mrow[row];
            float m_new = fmaxf(m_old, fmaxf(wmx[row], wmx[64+row]));
            float scl = __expf(m_old - m_new);
            float psum = 0.f;
            #pragma unroll
            for (int nt=0;nt<4;nt++){
                float p0 = __expf(sv[i][nt][0] - m_new);
                float p1 = __expf(sv[i][nt][1] - m_new);
                psum += p0 + p1;
                *(__half2*)&Ps[row*FQH + wn*32 + nt*8 + cg*2] = __floats2half2_rn(p0, p1);
                accO[nt][i*2+0] *= scl;
                accO[nt][i*2+1] *= scl;
            }
            psum += __shfl_xor_sync(0xffffffffu, psum, 1);
            psum += __shfl_xor_sync(0xffffffffu, psum, 2);
            if (cg == 0) wsm[wn*64 + row] = psum;
        }
        __syncthreads();

        if (tid < 64){
            float m_old = mrow[tid];
            float m_new = fmaxf(m_old, fmaxf(wmx[tid], wmx[64+tid]));
            lrow[tid] = lrow[tid]*__expf(m_old - m_new) + wsm[tid] + wsm[64+tid];
            mrow[tid] = m_new;
        }
        #pragma unroll
        for (int ks=0; ks<4; ks++){
            uint32_t af[4];
            ldsm_x4(af, smaddr(Ps + (wm*16 + rowL)*FQH + ks*16 + kHalf*8));
            #pragma unroll
            for (int nt=0; nt<2; nt++){
                uint32_t bf[4];
                ldsm_x4_t(bf, smaddr(Vs + (ks*16 + bKL)*FQH + wn*32 + nt*16 + bNH*8));
                mma_f16(accO[nt*2+0], af, bf[0], bf[1]);
                mma_f16(accO[nt*2+1], af, bf[2], bf[3]);
            }
        }
    }
    __syncthreads();

    #pragma unroll
    for (int i=0;i<2;i++){
        const int row = wm*16 + r + i*8;
        const int q   = qt0 + row;
        bool padq = (text[b*CTX_ + q] == PAD_);
        float inv = padq ? 0.f : 1.0f/lrow[row];
        #pragma unroll
        for (int nt=0;nt<4;nt++){
            int col = h*DH_ + wn*32 + nt*8 + cg*2;
            __half2 o2 = __floats2half2_rn(accO[nt][i*2+0]*inv, accO[nt][i*2+1]*inv);
            *(__half2*)(h_o + (size_t)(b*S_ + q)*D_ + col) = o2;
        }
    }
}

// ---------------- orchestration -----------------------------------------------
extern "C" void kernel_launch(void* const* d_in, const int* in_sizes, int n_in,
                              void* d_out, int out_size)
{
    (void)in_sizes; (void)n_in; (void)out_size;
    const int*   text = (const int*)  d_in[0];
    const float* emb  = (const float*)d_in[1];
    const float* u    = (const float*)d_in[2];
    const float* vbp  = (const float*)d_in[3];
    const float* Wq   = (const float*)d_in[4];
    const float* Wk   = (const float*)d_in[5];
    const float* Wv   = (const float*)d_in[6];
    const float* Wr   = (const float*)d_in[7];
    const float* Wfc  = (const float*)d_in[8];
    const float* bfc  = (const float*)d_in[9];
    const float* ln1g = (const float*)d_in[10];
    const float* ln1b = (const float*)d_in[11];
    const float* ln2g = (const float*)d_in[12];
    const float* ln2b = (const float*)d_in[13];
    const float* W1   = (const float*)d_in[14];
    const float* b1   = (const float*)d_in[15];
    const float* W2   = (const float*)d_in[16];
    const float* b2   = (const float*)d_in[17];
    const float* lnfg = (const float*)d_in[18];
    const float* lnfb = (const float*)d_in[19];
    const float* Wlm  = (const float*)d_in[20];
    const float* blm  = (const float*)d_in[21];
    float* out = (float*)d_out;

    float *px,*pxn;
    __half *pWq16,*pWk16,*pWv16,*pWr16,*pWfc16,*pW116,*pW216,*pWlm16,*pxn16,*po16,*pff16;
    cudaGetSymbolAddress((void**)&px,   g_x);
    cudaGetSymbolAddress((void**)&pxn,  g_xn);
    cudaGetSymbolAddress((void**)&pWq16, h_Wq);
    cudaGetSymbolAddress((void**)&pWk16, h_Wk);
    cudaGetSymbolAddress((void**)&pWv16, h_Wv);
    cudaGetSymbolAddress((void**)&pWr16, h_Wr);
    cudaGetSymbolAddress((void**)&pWfc16,h_Wfc);
    cudaGetSymbolAddress((void**)&pW116, h_W1);
    cudaGetSymbolAddress((void**)&pW216, h_W2);
    cudaGetSymbolAddress((void**)&pWlm16,h_Wlm);
    cudaGetSymbolAddress((void**)&pxn16, h_xn);
    cudaGetSymbolAddress((void**)&po16,  h_o);
    cudaGetSymbolAddress((void**)&pff16, h_ff);

    static bool attr_done = false;
    if (!attr_done){
        cudaFuncSetAttribute(flash_kernel, cudaFuncAttributeMaxDynamicSharedMemorySize, FL_SMEM);
        cudaFuncSetAttribute(qkvr_kernel,  cudaFuncAttributeMaxDynamicSharedMemorySize, HG_SMEM);
        cudaFuncSetAttribute((const void*)hgemm_kernel<1,float>,  cudaFuncAttributeMaxDynamicSharedMemorySize, HG_SMEM);
        cudaFuncSetAttribute((const void*)hgemm_kernel<2,__half>, cudaFuncAttributeMaxDynamicSharedMemorySize, HG_SMEM);
        cudaFuncSetAttribute((const void*)hgemm_kernel<3,float>,  cudaFuncAttributeMaxDynamicSharedMemorySize, HG_SMEM);
        cudaFuncSetAttribute((const void*)hgemm_kernel<4,float>,  cudaFuncAttributeMaxDynamicSharedMemorySize, HG_SMEM);
        attr_done = true;
    }

    const int MR = B_*S_;

    // ---- merged fp32 -> fp16 weight conversion (one launch) -----------------
    cvt_all_kernel<<<N8_TOTAL/256, 256>>>(
        (const float4*)Wq,  (const float4*)Wk,  (const float4*)Wv,  (const float4*)Wr,
        (const float4*)Wfc, (const float4*)W1,  (const float4*)W2,  (const float4*)Wlm);

    embed_kernel<<<2048,256>>>(text, emb);
    rel_kernel  <<<2048,256>>>();

    for (int l=0; l<L_; l++){
        ln_kernel<<<MR,256>>>(px, pxn, pxn16, ln1g + l*D_, ln1b + l*D_, 1);

        qkvr_kernel<<<dim3(MR/TBM, D_/TBN, 4),256, HG_SMEM>>>(l);

        bias_kernel <<<dim3(B_*S_, 2),256>>>(u, vbp);
        flash_kernel<<<dim3(16, B_*H_),256, FL_SMEM>>>(text);

        // x = x + xn + o@Wfc + bfc
        hgemm_kernel<3,float><<<dim3(MR/TBM, D_/TBN),256, HG_SMEM>>>(
            po16, pWfc16 + (size_t)l*D_*D_, bfc + l*D_, px, px, pxn, D_, D_);

        ln_kernel<<<MR,256>>>(px, pxn, pxn16, ln2g + l*D_, ln2b + l*D_, 0);
        hgemm_kernel<2,__half><<<dim3(MR/TBM, FF_/TBN),256, HG_SMEM>>>(
            pxn16, pW116 + (size_t)l*D_*FF_, b1 + l*FF_, pff16, nullptr, nullptr, FF_, D_);
        // x = x + gelu(ff@W2 + b2)
        hgemm_kernel<4,float><<<dim3(MR/TBM, D_/TBN),256, HG_SMEM>>>(
            pff16, pW216 + (size_t)l*FF_*D_, b2 + l*D_, px, px, nullptr, D_, FF_);
    }

    ln_kernel<<<MR,256>>>(px, pxn, pxn16, lnfg, lnfb, 0);
    hgemm_kernel<1,float><<<dim3(MR/TBM, V_/TBN),256, HG_SMEM>>>(
        pxn16, pWlm16, blm, out, nullptr, nullptr, V_, D_);
}

// round 17
// speedup vs baseline: 1.0333x; 1.0149x over previous
#include <cuda_runtime.h>
#include <cuda_fp16.h>
#include <stdint.h>
#include <math.h>

#define B_   2
#define S_   1024
#define D_   1024
#define H_   16
#define DH_  64
#define FF_  4096
#define V_   32000
#define L_   4
#define PAD_ 3
#define CTX_ 1025

// ---------------- scratch (fp32) ----------------------------------------------
__device__ float g_x  [B_*S_*D_];
__device__ float g_xn [B_*S_*D_];
__device__ float g_uk [B_*H_*S_];
__device__ float g_vr [H_*S_];

// ---------------- fp16 weights + activations -----------------------------------
__device__ __align__(16) __half h_Wq [L_*D_*D_];
__device__ __align__(16) __half h_Wk [L_*D_*D_];
__device__ __align__(16) __half h_Wv [L_*D_*D_];
__device__ __align__(16) __half h_Wr [L_*D_*D_];
__device__ __align__(16) __half h_Wfc[L_*D_*D_];
__device__ __align__(16) __half h_W1 [L_*D_*FF_];
__device__ __align__(16) __half h_W2 [L_*FF_*D_];
__device__ __align__(16) __half h_Wlm[(size_t)D_*V_];
__device__ __align__(16) __half h_xn [B_*S_*D_];
__device__ __align__(16) __half h_rel[S_*D_];
__device__ __align__(16) __half h_o  [B_*S_*D_];
__device__ __align__(16) __half h_ff [B_*S_*FF_];
__device__ __align__(16) __half h_q  [B_*S_*D_];
__device__ __align__(16) __half h_k  [B_*S_*D_];
__device__ __align__(16) __half h_v  [B_*S_*D_];
__device__ __align__(16) __half h_r  [S_*D_];

// ---------------- helpers --------------------------------------------------
__device__ __forceinline__ float gelu_t(float x){
    return 0.5f*x*(1.0f + tanhf(0.7978845608028654f*(x + 0.044715f*x*x*x)));
}
__device__ __forceinline__ uint32_t smaddr(const void* p){
    return (uint32_t)__cvta_generic_to_shared(p);
}
__device__ __forceinline__ void cp16(void* smem, const void* gmem){
    asm volatile("cp.async.cg.shared.global [%0], [%1], 16;\n"
        :: "r"(smaddr(smem)), "l"(gmem));
}
#define CP_COMMIT() asm volatile("cp.async.commit_group;\n" ::: "memory")
#define CP_WAIT(N)  asm volatile("cp.async.wait_group %0;\n" :: "n"(N) : "memory")

__device__ __forceinline__ void mma_f16(float c[4], const uint32_t a[4], const uint32_t b0, const uint32_t b1){
    asm volatile(
      "mma.sync.aligned.m16n8k16.row.col.f32.f16.f16.f32 "
      "{%0,%1,%2,%3}, {%4,%5,%6,%7}, {%8,%9}, {%0,%1,%2,%3};\n"
      : "+f"(c[0]), "+f"(c[1]), "+f"(c[2]), "+f"(c[3])
      : "r"(a[0]), "r"(a[1]), "r"(a[2]), "r"(a[3]), "r"(b0), "r"(b1));
}
__device__ __forceinline__ void ldsm_x4(uint32_t r[4], uint32_t addr){
    asm volatile("ldmatrix.sync.aligned.m8n8.x4.shared.b16 {%0,%1,%2,%3}, [%4];"
      : "=r"(r[0]), "=r"(r[1]), "=r"(r[2]), "=r"(r[3]) : "r"(addr));
}
__device__ __forceinline__ void ldsm_x4_t(uint32_t r[4], uint32_t addr){
    asm volatile("ldmatrix.sync.aligned.m8n8.x4.trans.shared.b16 {%0,%1,%2,%3}, [%4];"
      : "=r"(r[0]), "=r"(r[1]), "=r"(r[2]), "=r"(r[3]) : "r"(addr));
}

// ---------------- merged fp32 -> fp16 weight convert -------------------------
#define N8_DD (L_*D_*D_/8)
#define N8_DF (L_*D_*FF_/8)
#define N8_LM (D_*V_/8)
#define N8_TOTAL (5*N8_DD + 2*N8_DF + N8_LM)

__global__ void cvt_all_kernel(
    const float4* __restrict__ Wq,  const float4* __restrict__ Wk,
    const float4* __restrict__ Wv,  const float4* __restrict__ Wr,
    const float4* __restrict__ Wfc, const float4* __restrict__ W1,
    const float4* __restrict__ W2,  const float4* __restrict__ Wlm)
{
    int i = blockIdx.x*256 + threadIdx.x;
    const float4* src; uint4* dst; size_t j;
    if (i < 5*N8_DD){
        int t = i / N8_DD; j = i - t*N8_DD;
        src = (t==0)?Wq:(t==1)?Wk:(t==2)?Wv:(t==3)?Wr:Wfc;
        dst = (t==0)?(uint4*)h_Wq:(t==1)?(uint4*)h_Wk:(t==2)?(uint4*)h_Wv:(t==3)?(uint4*)h_Wr:(uint4*)h_Wfc;
    } else if (i < 5*N8_DD + 2*N8_DF){
        int k = i - 5*N8_DD; int t = k / N8_DF; j = k - t*N8_DF;
        src = t ? W2 : W1;
        dst = t ? (uint4*)h_W2 : (uint4*)h_W1;
    } else {
        j = i - (5*N8_DD + 2*N8_DF);
        src = Wlm; dst = (uint4*)h_Wlm;
    }
    float4 a = src[j*2], b = src[j*2+1];
    __half2 h0 = __floats2half2_rn(a.x, a.y);
    __half2 h1 = __floats2half2_rn(a.z, a.w);
    __half2 h2 = __floats2half2_rn(b.x, b.y);
    __half2 h3 = __floats2half2_rn(b.z, b.w);
    dst[j] = make_uint4(*(uint32_t*)&h0, *(uint32_t*)&h1, *(uint32_t*)&h2, *(uint32_t*)&h3);
}

// ---------------- embedding ------------------------------------------------
__global__ void embed_kernel(const int* __restrict__ text, const float* __restrict__ emb){
    int idx = blockIdx.x*256 + threadIdx.x;
    int d4  = idx & (D_/4 - 1);
    int bs  = idx >> 8;
    int s   = bs & (S_-1);
    int b   = bs >> 10;
    int tok = text[b*CTX_ + s];
    ((float4*)g_x)[idx] = ((const float4*)(emb + (size_t)tok*D_))[d4];
}

// ---------------- sinusoidal relative positions (fp16 out) ------------------
__global__ void rel_kernel(){
    int idx = blockIdx.x*256 + threadIdx.x;
    int j = idx & 511;
    int s = idx >> 9;
    float pos  = (float)(S_-1-s);
    float invf = powf(10000.0f, -(float)(2*j)/(float)D_);
    float a = pos*invf;
    h_rel[s*D_ + j]       = __float2half_rn(sinf(a));
    h_rel[s*D_ + j + 512] = __float2half_rn(cosf(a));
}

// ---------------- layernorm: one warp per row, no block barriers -------------
__global__ void __launch_bounds__(256)
ln_kernel(const float* __restrict__ in, float* __restrict__ out,
          __half* __restrict__ out16,
          const float* __restrict__ gam, const float* __restrict__ bet,
          int write32){
    const int w = threadIdx.x >> 5, lane = threadIdx.x & 31;
    const int row = blockIdx.x*8 + w;
    const float4* x4 = (const float4*)(in + (size_t)row*D_);

    float4 v[8];
    float s = 0.f, s2 = 0.f;
    #pragma unroll
    for (int i=0;i<8;i++){
        v[i] = x4[lane + i*32];
        s  += v[i].x + v[i].y + v[i].z + v[i].w;
        s2 += v[i].x*v[i].x + v[i].y*v[i].y + v[i].z*v[i].z + v[i].w*v[i].w;
    }
    #pragma unroll
    for (int o=16;o;o>>=1){
        s  += __shfl_xor_sync(0xffffffffu, s,  o);
        s2 += __shfl_xor_sync(0xffffffffu, s2, o);
    }
    const float m   = s * (1.0f/(float)D_);
    const float var = s2 * (1.0f/(float)D_) - m*m;
    const float inv = rsqrtf(var + 1e-5f);

    #pragma unroll
    for (int i=0;i<8;i++){
        float4 gg = ((const float4*)gam)[lane + i*32];
        float4 bb = ((const float4*)bet)[lane + i*32];
        float4 o4;
        o4.x = (v[i].x-m)*inv*gg.x + bb.x;
        o4.y = (v[i].y-m)*inv*gg.y + bb.y;
        o4.z = (v[i].z-m)*inv*gg.z + bb.z;
        o4.w = (v[i].w-m)*inv*gg.w + bb.w;
        if (write32)
            ((float4*)(out + (size_t)row*D_))[lane + i*32] = o4;
        __half2 p0 = __floats2half2_rn(o4.x, o4.y);
        __half2 p1 = __floats2half2_rn(o4.z, o4.w);
        *(uint2*)(out16 + (size_t)row*D_ + (lane + i*32)*4) =
            make_uint2(*(uint32_t*)&p0, *(uint32_t*)&p1);
    }
}

// ================= fp16 GEMM with cp.async 4-stage pipeline ==================
#define TBM 128
#define TBN 128
#define TBK 32
#define STAGES 4
#define HG_SMEM ((STAGES*TBM*40 + STAGES*TBK*136)*2)

// EPI: 0 plain | 1 +bias | 2 gelu(acc+bias) | 3 R1+R2+acc+bias | 4 R1+gelu(acc+bias)
template<int EPI, typename TC>
__device__ __forceinline__ void hgemm_body(
    const __half* __restrict__ A, const __half* __restrict__ Bm,
    const float* __restrict__ bias, TC* __restrict__ C,
    const float* __restrict__ R1, const float* __restrict__ R2,
    int N, int K)
{
    extern __shared__ __half hsm[];
    __half* Asm = hsm;
    __half* Bsm = hsm + STAGES*TBM*40;

    const int tid = threadIdx.x;
    const int lane = tid & 31, wid = tid >> 5;
    const int wm = wid >> 1, wn = wid & 1;
    const int r = lane >> 2, cg = lane & 3;
    const int bm = blockIdx.x*TBM, bn = blockIdx.y*TBN;

    const int arow = tid >> 1, ac0 = (tid & 1)*16;
    const int brow = tid >> 3, bc0 = (tid & 7)*16;

    const int aRowL = lane & 15, aKH = lane >> 4;
    const int bKL   = (lane & 7) + ((lane >> 3) & 1)*8, bNH = lane >> 4;

    float acc[2][8][4];
    #pragma unroll
    for (int mt=0;mt<2;mt++)
        #pragma unroll
        for (int nt=0;nt<8;nt++)
            #pragma unroll
            for (int i=0;i<4;i++) acc[mt][nt][i]=0.f;

    const int nkt = K/TBK;

    auto issue = [&](int kt, int s){
        __half* as = Asm + (s*TBM + arow)*40 + ac0;
        const __half* ap = A + (size_t)(bm+arow)*K + kt*TBK + ac0;
        cp16(as,   ap);
        cp16(as+8, ap+8);
        __half* bs = Bsm + (s*TBK + brow)*136 + bc0;
        const __half* bp = Bm + (size_t)(kt*TBK + brow)*N + bn + bc0;
        cp16(bs,   bp);
        cp16(bs+8, bp+8);
    };

    #pragma unroll
    for (int s=0; s<STAGES-1; s++){ issue(s, s); CP_COMMIT(); }

    for (int kt=0; kt<nkt; kt++){
        CP_WAIT(STAGES-2);
        __syncthreads();
        const int nk = kt + STAGES-1;
        if (nk < nkt) issue(nk, nk & (STAGES-1));
        CP_COMMIT();

        const int s = kt & (STAGES-1);
        const __half* as = Asm + (size_t)s*TBM*40;
        const __half* bs = Bsm + (size_t)s*TBK*136;
        #pragma unroll
        for (int ks=0; ks<2; ks++){
            uint32_t af[2][4];
            #pragma unroll
            for (int mt=0;mt<2;mt++)
                ldsm_x4(af[mt], smaddr(as + (wm*32 + mt*16 + aRowL)*40 + ks*16 + aKH*8));
            #pragma unroll
            for (int nt=0;nt<4;nt++){
                uint32_t bf[4];
                ldsm_x4_t(bf, smaddr(bs + (ks*16 + bKL)*136 + wn*64 + nt*16 + bNH*8));
                mma_f16(acc[0][nt*2+0], af[0], bf[0], bf[1]);
                mma_f16(acc[1][nt*2+0], af[1], bf[0], bf[1]);
                mma_f16(acc[0][nt*2+1], af[0], bf[2], bf[3]);
                mma_f16(acc[1][nt*2+1], af[1], bf[2], bf[3]);
            }
        }
    }

    #pragma unroll
    for (int mt=0;mt<2;mt++){
        int row0 = bm + wm*32 + mt*16 + r;
        #pragma unroll
        for (int nt=0;nt<8;nt++){
            int col = bn + wn*64 + nt*8 + cg*2;
            float2 b2 = make_float2(0.f,0.f);
            if (EPI >= 1) b2 = *(const float2*)(bias + col);
            float2 v0, v1;
            v0.x = acc[mt][nt][0] + b2.x; v0.y = acc[mt][nt][1] + b2.y;
            v1.x = acc[mt][nt][2] + b2.x; v1.y = acc[mt][nt][3] + b2.y;
            if (EPI == 2 || EPI == 4){
                v0.x = gelu_t(v0.x); v0.y = gelu_t(v0.y);
                v1.x = gelu_t(v1.x); v1.y = gelu_t(v1.y);
            }
            size_t i0 = (size_t)row0*N + col, i1 = (size_t)(row0+8)*N + col;
            if (EPI == 3){
                float2 a0 = *(const float2*)(R1 + i0), a1 = *(const float2*)(R1 + i1);
                float2 x0 = *(const float2*)(R2 + i0), x1 = *(const float2*)(R2 + i1);
                v0.x += a0.x + x0.x; v0.y += a0.y + x0.y;
                v1.x += a1.x + x1.x; v1.y += a1.y + x1.y;
            }
            if (EPI == 4){
                float2 a0 = *(const float2*)(R1 + i0), a1 = *(const float2*)(R1 + i1);
                v0.x += a0.x; v0.y += a0.y;
                v1.x += a1.x; v1.y += a1.y;
            }
            if constexpr (sizeof(TC) == 2){
                *(__half2*)(C + i0) = __floats2half2_rn(v0.x, v0.y);
                *(__half2*)(C + i1) = __floats2half2_rn(v1.x, v1.y);
            } else {
                *(float2*)(C + i0) = v0;
                *(float2*)(C + i1) = v1;
            }
        }
    }
}

template<int EPI, typename TC>
__global__ void __launch_bounds__(256, 2)
hgemm_kernel(const __half* __restrict__ A, const __half* __restrict__ Bm,
             const float* __restrict__ bias, TC* __restrict__ C,
             const float* __restrict__ R1, const float* __restrict__ R2,
             int N, int K)
{
    hgemm_body<EPI, TC>(A, Bm, bias, C, R1, R2, N, K);
}

__global__ void __launch_bounds__(256, 2)
qkvr_kernel(int l)
{
    const int z = blockIdx.z;
    if (z == 3 && blockIdx.x*TBM >= S_) return;
    const __half* A = (z < 3) ? h_xn : h_rel;
    const __half* W = ((z==0) ? h_Wq : (z==1) ? h_Wk : (z==2) ? h_Wv : h_Wr) + (size_t)l*D_*D_;
    __half*       C = (z==0) ? h_q : (z==1) ? h_k : (z==2) ? h_v : h_r;
    hgemm_body<0, __half>(A, W, nullptr, C, nullptr, nullptr, D_, D_);
}

// ---------------- bias precompute: uk[b,h,key]=u·k, vr[h,row]=v·r ----------
__global__ void bias_kernel(const float* __restrict__ uvec, const float* __restrict__ vvec){
    const int t = threadIdx.x;
    float4 uu;
    float2 f0, f1;
    if (blockIdx.y == 0){
        int row = blockIdx.x;
        uint2 raw = *(const uint2*)(h_k + (size_t)row*D_ + t*4);
        f0 = __half22float2(*(__half2*)&raw.x);
        f1 = __half22float2(*(__half2*)&raw.y);
        uu = ((const float4*)uvec)[t];
        float p = f0.x*uu.x + f0.y*uu.y + f1.x*uu.z + f1.y*uu.w;
        p += __shfl_xor_sync(0xffffffffu, p, 8);
        p += __shfl_xor_sync(0xffffffffu, p, 4);
        p += __shfl_xor_sync(0xffffffffu, p, 2);
        p += __shfl_xor_sync(0xffffffffu, p, 1);
        if ((t & 15) == 0){
            int h = t >> 4;
            int b = row >> 10, key = row & (S_-1);
            g_uk[((size_t)(b*H_ + h))*S_ + key] = p;
        }
    } else {
        int rrow = blockIdx.x;
        if (rrow >= S_) return;
        uint2 raw = *(const uint2*)(h_r + (size_t)rrow*D_ + t*4);
        f0 = __half22float2(*(__half2*)&raw.x);
        f1 = __half22float2(*(__half2*)&raw.y);
        uu = ((const float4*)vvec)[t];
        float p = f0.x*uu.x + f0.y*uu.y + f1.x*uu.z + f1.y*uu.w;
        p += __shfl_xor_sync(0xffffffffu, p, 8);
        p += __shfl_xor_sync(0xffffffffu, p, 4);
        p += __shfl_xor_sync(0xffffffffu, p, 2);
        p += __shfl_xor_sync(0xffffffffu, p, 1);
        if ((t & 15) == 0)
            g_vr[(t>>4)*S_ + rrow] = p;
    }
}

// ================= fused flash attention (R11-exact) =========================
#define FQH 72
#define FC2 132
#define FL_SMEM ((384*FQH)*2 + (64*FC2 + 128 + 128 + 64 + 64)*4)

__global__ void __launch_bounds__(256)
flash_kernel(const int* __restrict__ text){
    const int qtile = 15 - blockIdx.x;
    const int qt0 = qtile*64;
    const int bh = blockIdx.y, b = bh>>4, h = bh&15;

    extern __shared__ __half fsm[];
    __half* Qs = fsm;
    __half* Ks = Qs + 64*FQH;
    __half* Vs = Ks + 64*FQH;
    __half* Rs = Vs + 64*FQH;
    __half* Ps = Rs + 128*FQH;
    float*  C2  = (float*)(Ps + 64*FQH);
    float*  wmx = C2 + 64*FC2;
    float*  wsm = wmx + 128;
    float*  mrow = wsm + 128;
    float*  lrow = mrow + 64;

    const int tid = threadIdx.x;
    const int lane = tid&31, wid = tid>>5;
    const int wm = wid>>1, wn = wid&1;
    const int r = lane>>2, cg = lane&3;
    const int rowL = lane&15, kHalf = lane>>4;
    const int bKL = (lane&7) + ((lane>>3)&1)*8, bNH = lane>>4;

    {
        const int pos = tid>>2, c0 = (tid&3)*16;
        const __half* qp = h_q + ((size_t)(b*S_+qt0+pos))*D_ + h*DH_ + c0;
        *(uint4*)&Qs[pos*FQH+c0]   = *(const uint4*)qp;
        *(uint4*)&Qs[pos*FQH+c0+8] = *(const uint4*)(qp+8);
    }
    if (tid < 64){ mrow[tid] = -1e30f; lrow[tid] = 0.f; }

    float accO[4][4];
    #pragma unroll
    for (int nt=0;nt<4;nt++){ accO[nt][0]=accO[nt][1]=accO[nt][2]=accO[nt][3]=0.f; }

    const float* ukb = g_uk + (size_t)bh*S_;
    const float* vrp = g_vr + (size_t)h*S_;

    for (int kt=0; kt<=qtile; kt++){
        __syncthreads();
        {
            const int pos = tid>>2, c0 = (tid&3)*16;
            const __half* kp = h_k + ((size_t)(b*S_+kt*64+pos))*D_ + h*DH_ + c0;
            *(uint4*)&Ks[pos*FQH+c0]   = *(const uint4*)kp;
            *(uint4*)&Ks[pos*FQH+c0+8] = *(const uint4*)(kp+8);
            const __half* vp = h_v + ((size_t)(b*S_+kt*64+pos))*D_ + h*DH_ + c0;
            *(uint4*)&Vs[pos*FQH+c0]   = *(const uint4*)vp;
            *(uint4*)&Vs[pos*FQH+c0+8] = *(const uint4*)(vp+8);
        }
        {
            const int rbase = S_ - 64 - qt0 + kt*64;
            const int j = tid>>1, rc0 = (tid&1)*32;
            const int rrow = rbase + j;
            if (rrow >= 0 && rrow < S_ && j < 127){
                const __half* rp = h_r + (size_t)rrow*D_ + h*DH_ + rc0;
                #pragma unroll
                for (int c=0;c<4;c++)
                    *(uint4*)&Rs[j*FQH + rc0 + c*8] = *(const uint4*)(rp + c*8);
            } else {
                uint4 z = make_uint4(0,0,0,0);
                #pragma unroll
                for (int c=0;c<4;c++)
                    *(uint4*)&Rs[j*FQH + rc0 + c*8] = z;
            }
        }
        __syncthreads();

        float accA[4][4], accB[8][4];
        #pragma unroll
        for (int nt=0;nt<4;nt++){ accA[nt][0]=accA[nt][1]=accA[nt][2]=accA[nt][3]=0.f; }
        #pragma unroll
        for (int nt=0;nt<8;nt++){ accB[nt][0]=accB[nt][1]=accB[nt][2]=accB[nt][3]=0.f; }
        #pragma unroll
        for (int ks=0; ks<4; ks++){
            uint32_t a[4];
            ldsm_x4(a, smaddr(Qs + (wm*16 + rowL)*FQH + ks*16 + kHalf*8));
            #pragma unroll
            for (int np=0; np<2; np++){
                uint32_t bk[4];
                ldsm_x4(bk, smaddr(Ks + (wn*32 + np*16 + rowL)*FQH + ks*16 + kHalf*8));
                mma_f16(accA[np*2+0], a, bk[0], bk[2]);
                mma_f16(accA[np*2+1], a, bk[1], bk[3]);
            }
            #pragma unroll
            for (int np=0; np<4; np++){
                uint32_t br[4];
                ldsm_x4(br, smaddr(Rs + (wn*64 + np*16 + rowL)*FQH + ks*16 + kHalf*8));
                mma_f16(accB[np*2+0], a, br[0], br[2]);
                mma_f16(accB[np*2+1], a, br[1], br[3]);
            }
        }
        #pragma unroll
        for (int nt=0;nt<8;nt++){
            int col = wn*64 + nt*8 + cg*2;
            C2[(wm*16+r  )*FC2 + col    ] = accB[nt][0];
            C2[(wm*16+r  )*FC2 + col + 1] = accB[nt][1];
            C2[(wm*16+r+8)*FC2 + col    ] = accB[nt][2];
            C2[(wm*16+r+8)*FC2 + col + 1] = accB[nt][3];
        }
        __syncthreads();

        const float* ukp = ukb + kt*64;
        float sv[2][4][2];
        float tmax[2] = {-1e30f, -1e30f};
        #pragma unroll
        for (int i=0;i<2;i++){
            const int qr = wm*16 + r + i*8;
            const int q  = qt0 + qr;
            #pragma unroll
            for (int nt=0;nt<4;nt++){
                #pragma unroll
                for (int cc=0;cc<2;cc++){
                    const int kr = wn*32 + nt*8 + cg*2 + cc;
                    const int k  = kt*64 + kr;
                    float v;
                    if (k <= q){
                        v = (accA[nt][i*2+cc] + ukp[kr]
                             + C2[qr*FC2 + 63 + kr - qr] + vrp[S_-1-q+k]) * 0.125f;
                    } else v = -1e30f;
                    sv[i][nt][cc] = v;
                    tmax[i] = fmaxf(tmax[i], v);
                }
            }
        }
        #pragma unroll
        for (int i=0;i<2;i++){
            tmax[i] = fmaxf(tmax[i], __shfl_xor_sync(0xffffffffu, tmax[i], 1));
            tmax[i] = fmaxf(tmax[i], __shfl_xor_sync(0xffffffffu, tmax[i], 2));
        }
        if (cg == 0){
            wmx[wn*64 + wm*16 + r    ] = tmax[0];
            wmx[wn*64 + wm*16 + r + 8] = tmax[1];
        }
        __syncthreads();

        #pragma unroll
        for (int i=0;i<2;i++){
            const int row = wm*16 + r + i*8;
            float m_old = mrow[row];
            float m_new = fmaxf(m_old, fmaxf(wmx[row], wmx[64+row]));
            float scl = __expf(m_old - m_new);
            float psum = 0.f;
            #pragma unroll
            for (int nt=0;nt<4;nt++){
                float p0 = __expf(sv[i][nt][0] - m_new);
                float p1 = __expf(sv[i][nt][1] - m_new);
                psum += p0 + p1;
                *(__half2*)&Ps[row*FQH + wn*32 + nt*8 + cg*2] = __floats2half2_rn(p0, p1);
                accO[nt][i*2+0] *= scl;
                accO[nt][i*2+1] *= scl;
            }
            psum += __shfl_xor_sync(0xffffffffu, psum, 1);
            psum += __shfl_xor_sync(0xffffffffu, psum, 2);
            if (cg == 0) wsm[wn*64 + row] = psum;
        }
        __syncthreads();

        if (tid < 64){
            float m_old = mrow[tid];
            float m_new = fmaxf(m_old, fmaxf(wmx[tid], wmx[64+tid]));
            lrow[tid] = lrow[tid]*__expf(m_old - m_new) + wsm[tid] + wsm[64+tid];
            mrow[tid] = m_new;
        }
        #pragma unroll
        for (int ks=0; ks<4; ks++){
            uint32_t af[4];
            ldsm_x4(af, smaddr(Ps + (wm*16 + rowL)*FQH + ks*16 + kHalf*8));
            #pragma unroll
            for (int nt=0; nt<2; nt++){
                uint32_t bf[4];
                ldsm_x4_t(bf, smaddr(Vs + (ks*16 + bKL)*FQH + wn*32 + nt*16 + bNH*8));
                mma_f16(accO[nt*2+0], af, bf[0], bf[1]);
                mma_f16(accO[nt*2+1], af, bf[2], bf[3]);
            }
        }
    }
    __syncthreads();

    #pragma unroll
    for (int i=0;i<2;i++){
        const int row = wm*16 + r + i*8;
        const int q   = qt0 + row;
        bool padq = (text[b*CTX_ + q] == PAD_);
        float inv = padq ? 0.f : 1.0f/lrow[row];
        #pragma unroll
        for (int nt=0;nt<4;nt++){
            int col = h*DH_ + wn*32 + nt*8 + cg*2;
            __half2 o2 = __floats2half2_rn(accO[nt][i*2+0]*inv, accO[nt][i*2+1]*inv);
            *(__half2*)(h_o + (size_t)(b*S_ + q)*D_ + col) = o2;
        }
    }
}

// ---------------- orchestration -----------------------------------------------
extern "C" void kernel_launch(void* const* d_in, const int* in_sizes, int n_in,
                              void* d_out, int out_size)
{
    (void)in_sizes; (void)n_in; (void)out_size;
    const int*   text = (const int*)  d_in[0];
    const float* emb  = (const float*)d_in[1];
    const float* u    = (const float*)d_in[2];
    const float* vbp  = (const float*)d_in[3];
    const float* Wq   = (const float*)d_in[4];
    const float* Wk   = (const float*)d_in[5];
    const float* Wv   = (const float*)d_in[6];
    const float* Wr   = (const float*)d_in[7];
    const float* Wfc  = (const float*)d_in[8];
    const float* bfc  = (const float*)d_in[9];
    const float* ln1g = (const float*)d_in[10];
    const float* ln1b = (const float*)d_in[11];
    const float* ln2g = (const float*)d_in[12];
    const float* ln2b = (const float*)d_in[13];
    const float* W1   = (const float*)d_in[14];
    const float* b1   = (const float*)d_in[15];
    const float* W2   = (const float*)d_in[16];
    const float* b2   = (const float*)d_in[17];
    const float* lnfg = (const float*)d_in[18];
    const float* lnfb = (const float*)d_in[19];
    const float* Wlm  = (const float*)d_in[20];
    const float* blm  = (const float*)d_in[21];
    float* out = (float*)d_out;

    float *px,*pxn;
    __half *pWq16,*pWk16,*pWv16,*pWr16,*pWfc16,*pW116,*pW216,*pWlm16,*pxn16,*po16,*pff16;
    cudaGetSymbolAddress((void**)&px,   g_x);
    cudaGetSymbolAddress((void**)&pxn,  g_xn);
    cudaGetSymbolAddress((void**)&pWq16, h_Wq);
    cudaGetSymbolAddress((void**)&pWk16, h_Wk);
    cudaGetSymbolAddress((void**)&pWv16, h_Wv);
    cudaGetSymbolAddress((void**)&pWr16, h_Wr);
    cudaGetSymbolAddress((void**)&pWfc16,h_Wfc);
    cudaGetSymbolAddress((void**)&pW116, h_W1);
    cudaGetSymbolAddress((void**)&pW216, h_W2);
    cudaGetSymbolAddress((void**)&pWlm16,h_Wlm);
    cudaGetSymbolAddress((void**)&pxn16, h_xn);
    cudaGetSymbolAddress((void**)&po16,  h_o);
    cudaGetSymbolAddress((void**)&pff16, h_ff);

    static bool attr_done = false;
    if (!attr_done){
        cudaFuncSetAttribute(flash_kernel, cudaFuncAttributeMaxDynamicSharedMemorySize, FL_SMEM);
        cudaFuncSetAttribute(qkvr_kernel,  cudaFuncAttributeMaxDynamicSharedMemorySize, HG_SMEM);
        cudaFuncSetAttribute((const void*)hgemm_kernel<1,float>,  cudaFuncAttributeMaxDynamicSharedMemorySize, HG_SMEM);
        cudaFuncSetAttribute((const void*)hgemm_kernel<2,__half>, cudaFuncAttributeMaxDynamicSharedMemorySize, HG_SMEM);
        cudaFuncSetAttribute((const void*)hgemm_kernel<3,float>,  cudaFuncAttributeMaxDynamicSharedMemorySize, HG_SMEM);
        cudaFuncSetAttribute((const void*)hgemm_kernel<4,float>,  cudaFuncAttributeMaxDynamicSharedMemorySize, HG_SMEM);
        attr_done = true;
    }

    const int MR = B_*S_;

    // ---- merged fp32 -> fp16 weight conversion (one launch) -----------------
    cvt_all_kernel<<<N8_TOTAL/256, 256>>>(
        (const float4*)Wq,  (const float4*)Wk,  (const float4*)Wv,  (const float4*)Wr,
        (const float4*)Wfc, (const float4*)W1,  (const float4*)W2,  (const float4*)Wlm);

    embed_kernel<<<2048,256>>>(text, emb);
    rel_kernel  <<<2048,256>>>();

    for (int l=0; l<L_; l++){
        ln_kernel<<<MR/8,256>>>(px, pxn, pxn16, ln1g + l*D_, ln1b + l*D_, 1);

        qkvr_kernel<<<dim3(MR/TBM, D_/TBN, 4),256, HG_SMEM>>>(l);

        bias_kernel <<<dim3(B_*S_, 2),256>>>(u, vbp);
        flash_kernel<<<dim3(16, B_*H_),256, FL_SMEM>>>(text);

        // x = x + xn + o@Wfc + bfc
        hgemm_kernel<3,float><<<dim3(MR/TBM, D_/TBN),256, HG_SMEM>>>(
            po16, pWfc16 + (size_t)l*D_*D_, bfc + l*D_, px, px, pxn, D_, D_);

        ln_kernel<<<MR/8,256>>>(px, pxn, pxn16, ln2g + l*D_, ln2b + l*D_, 0);
        hgemm_kernel<2,__half><<<dim3(MR/TBM, FF_/TBN),256, HG_SMEM>>>(
            pxn16, pW116 + (size_t)l*D_*FF_, b1 + l*FF_, pff16, nullptr, nullptr, FF_, D_);
        // x = x + gelu(ff@W2 + b2)
        hgemm_kernel<4,float><<<dim3(MR/TBM, D_/TBN),256, HG_SMEM>>>(
            pff16, pW216 + (size_t)l*FF_*D_, b2 + l*D_, px, px, nullptr, D_, FF_);
    }

    ln_kernel<<<MR/8,256>>>(px, pxn, pxn16, lnfg, lnfb, 0);
    hgemm_kernel<1,float><<<dim3(MR/TBM, V_/TBN),256, HG_SMEM>>>(
        pxn16, pWlm16, blm, out, nullptr, nullptr, V_, D_);
}